// round 14
// baseline (speedup 1.0000x reference)
#include <cuda_runtime.h>
#include <cuda_fp16.h>
#include <math.h>
#include <stdint.h>

#define BB 2
#define LL 2048
#define DD 1024
#define HH 4
#define DV 256
#define CKN 32
#define NC 64              // LL / CKN
#define NROW (BB*LL)       // 4096
#define GIN 1056
#define GINP 1088          // padded to multiple of 64
#define HID 2048
#define NG 8               // Dv groups of 32 in the scan

// ------------------------- scratch (device globals) -------------------------
__device__ float g_beta[NROW*HH];
__device__ float g_hmid[NROW*HID];
__device__ float g_probs[NROW*16];
// fp16 intermediates + GEMM operands
__device__ __half g_qn_h[NROW*DD];       // [bh][c][time32][dv256]
__device__ __half g_knT_h[NROW*DD];      // [bh][c][dv256][time32]
__device__ __half g_u_h[NROW*DD];        // [bh][c][time32][dv256]
__device__ __half g_w_h[NROW*DD];        // [bh][c][time32][dv256]
__device__ __half g_attn_h[BB*HH*NC*CKN*CKN];
__device__ __half g_delta_h[NROW*DD];
__device__ __half g_short_h[NROW*DD];
__device__ __half g_long_h[NROW*DD];
__device__ __half g_qlin_h[NROW*DD];
__device__ __half g_klin_h[NROW*DD];
__device__ __half g_vlin_h[NROW*DD];
__device__ __half g_qc_h[NROW*DD];
__device__ __half g_kc_h[NROW*DD];
__device__ __half g_vc_h[NROW*DD];
__device__ __half g_hs_h[NROW*DD];
__device__ __half g_wq_h[DD*DD];
__device__ __half g_wk_h[DD*DD];
__device__ __half g_wv_h[DD*DD];
__device__ __half g_wo_h[DD*DD];
__device__ __half g_gw1_h[HID*GINP];
__device__ __half g_gatein_h[NROW*GINP];
__device__ __half g_mix_h[NROW*DD];

// ------------------------- helpers ------------------------------------------
__device__ __forceinline__ unsigned f2tf(float x) {
    unsigned r;
    asm("cvt.rna.tf32.f32 %0, %1;" : "=r"(r) : "f"(x));
    return r;
}

__device__ __forceinline__ void mma_tf32(float* c, const unsigned* a, const unsigned* b) {
    asm volatile(
        "mma.sync.aligned.m16n8k8.row.col.f32.tf32.tf32.f32 "
        "{%0,%1,%2,%3}, {%4,%5,%6,%7}, {%8,%9}, {%0,%1,%2,%3};"
        : "+f"(c[0]), "+f"(c[1]), "+f"(c[2]), "+f"(c[3])
        : "r"(a[0]), "r"(a[1]), "r"(a[2]), "r"(a[3]), "r"(b[0]), "r"(b[1]));
}

__device__ __forceinline__ void mma_f16(float* c, const unsigned* a, const unsigned* b) {
    asm volatile(
        "mma.sync.aligned.m16n8k16.row.col.f32.f16.f16.f32 "
        "{%0,%1,%2,%3}, {%4,%5,%6,%7}, {%8,%9}, {%0,%1,%2,%3};"
        : "+f"(c[0]), "+f"(c[1]), "+f"(c[2]), "+f"(c[3])
        : "r"(a[0]), "r"(a[1]), "r"(a[2]), "r"(a[3]), "r"(b[0]), "r"(b[1]));
}

#define LDSM4(r, addr)                                                        \
    asm volatile("ldmatrix.sync.aligned.m8n8.x4.shared.b16 {%0,%1,%2,%3}, [%4];" \
        : "=r"((r)[0]), "=r"((r)[1]), "=r"((r)[2]), "=r"((r)[3]) : "r"(addr))

// ------------------------- bulk fp32 -> fp16 conversion ---------------------
__global__ __launch_bounds__(256) void cvt_h6(
    const float* __restrict__ s0, __half* __restrict__ d0, int n0,
    const float* __restrict__ s1, __half* __restrict__ d1, int n1,
    const float* __restrict__ s2, __half* __restrict__ d2, int n2,
    const float* __restrict__ s3, __half* __restrict__ d3, int n3,
    const float* __restrict__ s4, __half* __restrict__ d4, int n4,
    const float* __restrict__ s5, __half* __restrict__ d5, int n5)
{
    const float* s; __half* d; int n;
    switch (blockIdx.y) {
        case 0: s=s0; d=d0; n=n0; break;
        case 1: s=s1; d=d1; n=n1; break;
        case 2: s=s2; d=d2; n=n2; break;
        case 3: s=s3; d=d3; n=n3; break;
        case 4: s=s4; d=d4; n=n4; break;
        default: s=s5; d=d5; n=n5; break;
    }
    int i = (blockIdx.x * 256 + threadIdx.x) * 4;
    if (i < n) {
        float4 v = *(const float4*)(s + i);
        __half2 lo = __floats2half2_rn(v.x, v.y);
        __half2 hi = __floats2half2_rn(v.z, v.w);
        uint2 o = {*(unsigned*)&lo, *(unsigned*)&hi};
        *(uint2*)(d + i) = o;
    }
}

// --------- gate_w1 fp32[HID][GIN] -> fp16[HID][GINP] with zero pad ----------
__global__ __launch_bounds__(256) void cvt_gw1pad(const float* __restrict__ src)
{
    int i = (blockIdx.x * 256 + threadIdx.x) * 4;
    if (i >= HID*GINP) return;
    int row = i / GINP, col = i % GINP;
    float4 v;
    if (col < GIN) v = *(const float4*)&src[(size_t)row*GIN + col];
    else v = make_float4(0.f, 0.f, 0.f, 0.f);
    __half2 lo = __floats2half2_rn(v.x, v.y);
    __half2 hi = __floats2half2_rn(v.z, v.w);
    uint2 o = {*(unsigned*)&lo, *(unsigned*)&hi};
    *(uint2*)&g_gw1_h[i] = o;
}

// ---------------- fp16 tensor GEMM: C = A(MxK) @ B(NxK)^T -------------------
// K=64 per stage, 3-stage cp.async pipeline (wait_group 1), 128x128 tile.
// Smem rows: 64 halves @ 144B stride (LDSM conflict-free).
// mode 0: fp32 out.  mode 1: +bias, exact GELU, fp32 out.  mode 2: fp16 out.
#define HSTRB 144
#define HSTAGE_BYTES (128*HSTRB)        // 18432
#define HGEMM_SMEM (6*HSTAGE_BYTES)     // 110592

#define HLOAD64(kt, st) do {                                                   \
    const __half* Ap_ = A + (size_t)bm*K + (kt)*64;                            \
    const __half* Bp_ = B + (size_t)bn*K + (kt)*64;                            \
    _Pragma("unroll")                                                          \
    for (int i_ = 0; i_ < 4; i_++) {                                           \
        int e_ = tid + i_*256;                                                 \
        int row_ = e_ >> 3, seg_ = e_ & 7;                                     \
        unsigned doff_ = (unsigned)row_*HSTRB + (unsigned)seg_*16;             \
        asm volatile("cp.async.cg.shared.global [%0], [%1], 16;"               \
            :: "r"(smb + (unsigned)((st)*HSTAGE_BYTES) + doff_),               \
               "l"(Ap_ + (size_t)row_*K + seg_*8));                            \
        asm volatile("cp.async.cg.shared.global [%0], [%1], 16;"               \
            :: "r"(smb + (unsigned)(3*HSTAGE_BYTES + (st)*HSTAGE_BYTES) + doff_), \
               "l"(Bp_ + (size_t)row_*K + seg_*8));                            \
    }                                                                          \
} while (0)

__global__ __launch_bounds__(256, 2) void hgemm(
    const __half* __restrict__ A,
    const __half* __restrict__ Bm0, const __half* __restrict__ Bm1, const __half* __restrict__ Bm2,
    float* __restrict__ Cm0, float* __restrict__ Cm1, float* __restrict__ Cm2,
    const float* __restrict__ bias, int M, int N, int K, int mode)
{
    extern __shared__ char tsm[];

    const __half* B = (blockIdx.z == 0) ? Bm0 : (blockIdx.z == 1) ? Bm1 : Bm2;
    float*        C = (blockIdx.z == 0) ? Cm0 : (blockIdx.z == 1) ? Cm1 : Cm2;

    int tid = threadIdx.x;
    int bm = blockIdx.y * 128, bn = blockIdx.x * 128;
    unsigned smb;
    asm("{ .reg .u64 t; cvta.to.shared.u64 t, %1; cvt.u32.u64 %0, t; }"
        : "=r"(smb) : "l"(tsm));

    int wid = tid >> 5, lane = tid & 31;
    int wm = (wid >> 2) * 64, wn = (wid & 3) * 32;
    int lr = lane >> 2, lk = lane & 3;

    int a_row = (lane & 7) + ((lane >> 3) & 1) * 8;
    int a_kb  = (lane >> 4) * 16;
    int b_row = (lane & 7) + ((lane >> 4) & 1) * 8;
    int b_kb  = ((lane >> 3) & 1) * 16;

    float acc[4][4][4];
#pragma unroll
    for (int mi = 0; mi < 4; mi++)
#pragma unroll
        for (int ni = 0; ni < 4; ni++)
#pragma unroll
            for (int j = 0; j < 4; j++) acc[mi][ni][j] = 0.f;

    int niter = K >> 6;

    HLOAD64(0, 0);
    asm volatile("cp.async.commit_group;");
    if (niter > 1) HLOAD64(1, 1);
    asm volatile("cp.async.commit_group;");

    for (int t = 0; t < niter; t++) {
        asm volatile("cp.async.wait_group 1;");
        __syncthreads();
        if (t + 2 < niter) HLOAD64(t + 2, (t + 2) % 3);
        asm volatile("cp.async.commit_group;");

        int cur = t % 3;
        unsigned a_base = smb + (unsigned)(cur*HSTAGE_BYTES);
        unsigned b_base = smb + (unsigned)(3*HSTAGE_BYTES + cur*HSTAGE_BYTES);
#pragma unroll
        for (int ks = 0; ks < 4; ks++) {
            unsigned af[4][4], bq[2][4];
#pragma unroll
            for (int mi = 0; mi < 4; mi++) {
                unsigned addr = a_base + (unsigned)((wm + mi*16 + a_row)*HSTRB + ks*32 + a_kb);
                LDSM4(af[mi], addr);
            }
#pragma unroll
            for (int nq = 0; nq < 2; nq++) {
                unsigned addr = b_base + (unsigned)((wn + nq*16 + b_row)*HSTRB + ks*32 + b_kb);
                LDSM4(bq[nq], addr);
            }
#pragma unroll
            for (int mi = 0; mi < 4; mi++)
#pragma unroll
                for (int ni = 0; ni < 4; ni++)
                    mma_f16(acc[mi][ni], af[mi], &bq[ni >> 1][(ni & 1) * 2]);
        }
        __syncthreads();
    }

#pragma unroll
    for (int mi = 0; mi < 4; mi++) {
        int r0 = bm + wm + mi*16 + lr;
#pragma unroll
        for (int ni = 0; ni < 4; ni++) {
            int c = bn + wn + ni*8 + 2*lk;
            float v[4] = {acc[mi][ni][0], acc[mi][ni][1], acc[mi][ni][2], acc[mi][ni][3]};
            if (mode == 1) {
                float b0 = bias[c], b1 = bias[c+1];
                v[0] += b0; v[1] += b1; v[2] += b0; v[3] += b1;
#pragma unroll
                for (int j = 0; j < 4; j++)
                    v[j] = 0.5f * v[j] * (1.f + erff(v[j] * 0.70710678118654752f));
            }
            if (mode == 2) {
                __half* Ch = (__half*)C;
                *(__half2*)&Ch[(size_t)r0*N + c]     = __floats2half2_rn(v[0], v[1]);
                *(__half2*)&Ch[(size_t)(r0+8)*N + c] = __floats2half2_rn(v[2], v[3]);
            } else {
                float2 lo = {v[0], v[1]};
                float2 hi = {v[2], v[3]};
                *(float2*)&C[(size_t)r0*N + c]       = lo;
                *(float2*)&C[(size_t)(r0+8)*N + c]   = hi;
            }
        }
    }
}

// ------------- depthwise causal conv4 + SiLU, fp16 io, 4 elems/thread -------
__global__ __launch_bounds__(256) void conv4_silu3(
    const __half* __restrict__ x0, const __half* __restrict__ x1, const __half* __restrict__ x2,
    const float* __restrict__ w0, const float* __restrict__ w1, const float* __restrict__ w2,
    __half* __restrict__ y0, __half* __restrict__ y1, __half* __restrict__ y2)
{
    const __half* x; const float* w; __half* y;
    if (blockIdx.y == 0)      { x = x0; w = w0; y = y0; }
    else if (blockIdx.y == 1) { x = x1; w = w1; y = y1; }
    else                      { x = x2; w = w2; y = y2; }
    int q = blockIdx.x * 256 + threadIdx.x;     // quad index over NROW*DD/4
    int dq = q & (DD/4 - 1);
    int l = (q >> 8) & (LL - 1);
    int d = dq * 4;
    float4 w0v = *(const float4*)(w + d*4);
    float4 w1v = *(const float4*)(w + d*4 + 4);
    float4 w2v = *(const float4*)(w + d*4 + 8);
    float4 w3v = *(const float4*)(w + d*4 + 12);
    const uint2* xp = (const uint2*)x + q;
    uint2 raw = xp[0];
    float2 xa = __half22float2(*(__half2*)&raw.x);
    float2 xb = __half22float2(*(__half2*)&raw.y);
    float a0 = w0v.w * xa.x, a1 = w1v.w * xa.y, a2 = w2v.w * xb.x, a3 = w3v.w * xb.y;
    if (l >= 1) {
        uint2 t = xp[-(DD/4)];
        float2 ta = __half22float2(*(__half2*)&t.x);
        float2 tb = __half22float2(*(__half2*)&t.y);
        a0 += w0v.z*ta.x; a1 += w1v.z*ta.y; a2 += w2v.z*tb.x; a3 += w3v.z*tb.y;
    }
    if (l >= 2) {
        uint2 t = xp[-(DD/2)];
        float2 ta = __half22float2(*(__half2*)&t.x);
        float2 tb = __half22float2(*(__half2*)&t.y);
        a0 += w0v.y*ta.x; a1 += w1v.y*ta.y; a2 += w2v.y*tb.x; a3 += w3v.y*tb.y;
    }
    if (l >= 3) {
        uint2 t = xp[-(3*DD/4)];
        float2 ta = __half22float2(*(__half2*)&t.x);
        float2 tb = __half22float2(*(__half2*)&t.y);
        a0 += w0v.x*ta.x; a1 += w1v.x*ta.y; a2 += w2v.x*tb.x; a3 += w3v.x*tb.y;
    }
    a0 = a0 / (1.f + __expf(-a0));
    a1 = a1 / (1.f + __expf(-a1));
    a2 = a2 / (1.f + __expf(-a2));
    a3 = a3 / (1.f + __expf(-a3));
    __half2 o0 = __floats2half2_rn(a0, a1);
    __half2 o1 = __floats2half2_rn(a2, a3);
    uint2 ov = {*(unsigned*)&o0, *(unsigned*)&o1};
    ((uint2*)y)[q] = ov;
}

// ------------------------- beta = sigmoid(hs @ Wb^T) ------------------------
__global__ __launch_bounds__(128) void beta_kernel(
    const float* __restrict__ hs, const float* __restrict__ Wb)
{
    __shared__ float red[4][128];
    int n = blockIdx.x, tid = threadIdx.x;
    const float* hr = hs + (size_t)n * DD;
    float s0=0,s1=0,s2=0,s3=0;
    for (int i = tid; i < DD; i += 128) {
        float x = hr[i];
        s0 += x * Wb[i];
        s1 += x * Wb[DD + i];
        s2 += x * Wb[2*DD + i];
        s3 += x * Wb[3*DD + i];
    }
    red[0][tid]=s0; red[1][tid]=s1; red[2][tid]=s2; red[3][tid]=s3;
    __syncthreads();
    for (int st = 64; st > 0; st >>= 1) {
        if (tid < st)
#pragma unroll
            for (int h = 0; h < 4; h++) red[h][tid] += red[h][tid + st];
        __syncthreads();
    }
    if (tid < 4) g_beta[(size_t)n*HH + tid] = 1.f / (1.f + expf(-red[tid][0]));
}

// ---------------- per-chunk delta-rule precompute (tensor-core mma) ---------
// Outputs fp16: qn [t][d], w/u [t][d], knT [d][t], attn [t][t].
#define PSTR 264
#define PSMEM ((2*32*PSTR + 32*33 + 32*36 + 96) * 4)
__global__ __launch_bounds__(256) void precompute_kernel()
{
    extern __shared__ float psm[];
    float*    Kt  = psm;                     // [32][PSTR] k fp32 -> kn tf32
    float*    Qt  = Kt + 32*PSTR;            // [32][PSTR] q fp32 -> qn tf32 -> v tf32
    float*    Am  = Qt + 32*PSTR;            // [32][33]
    unsigned* Ttf = (unsigned*)(Am + 32*33); // [32][36]
    float*    bet = (float*)(Ttf + 32*36);   // [32]
    float*    rnk = bet + 32;                // [32]
    float*    rnq = rnk + 32;                // [32]

    int blk = blockIdx.x;           // (b*HH + h)*NC + c
    int c  = blk % NC;
    int bh = blk / NC;
    int h  = bh % HH;
    int b  = bh / HH;
    int tid = threadIdx.x;
    int l0 = c * 32;
    int wid = tid >> 5, lane = tid & 31;
    int lr = lane >> 2, lk = lane & 3;

    // 1. load k, q tiles (fp16 -> fp32)
    for (int e = tid*4; e < 32*256; e += 1024) {
        int r = e >> 8, d = e & 255;
        size_t gb = ((size_t)(b*LL + l0 + r))*DD + h*DV + d;
        uint2 kh = *(const uint2*)&g_kc_h[gb];
        float2 ka = __half22float2(*(__half2*)&kh.x);
        float2 kb2 = __half22float2(*(__half2*)&kh.y);
        *(float4*)&Kt[r*PSTR + d] = make_float4(ka.x, ka.y, kb2.x, kb2.y);
        uint2 qh = *(const uint2*)&g_qc_h[gb];
        float2 qa = __half22float2(*(__half2*)&qh.x);
        float2 qb2 = __half22float2(*(__half2*)&qh.y);
        *(float4*)&Qt[r*PSTR + d] = make_float4(qa.x, qa.y, qb2.x, qb2.y);
    }
    if (tid < 32) bet[tid] = g_beta[((size_t)(b*LL + l0 + tid))*HH + h];
    __syncthreads();

    // 2. row norms (8 threads per row)
    {
        int r = tid >> 3, part = tid & 7;
        float sk = 0.f, sq = 0.f;
        for (int j = part*32; j < part*32 + 32; j++) {
            float x = Kt[r*PSTR + j]; sk += x*x;
            float y = Qt[r*PSTR + j]; sq += y*y;
        }
        sk += __shfl_down_sync(0xffffffffu, sk, 4, 8);
        sk += __shfl_down_sync(0xffffffffu, sk, 2, 8);
        sk += __shfl_down_sync(0xffffffffu, sk, 1, 8);
        sq += __shfl_down_sync(0xffffffffu, sq, 4, 8);
        sq += __shfl_down_sync(0xffffffffu, sq, 2, 8);
        sq += __shfl_down_sync(0xffffffffu, sq, 1, 8);
        if (part == 0) { rnk[r] = rsqrtf(sk + 1e-6f); rnq[r] = rsqrtf(sq + 1e-6f); }
    }
    __syncthreads();

    // 3. normalize in place (qn fp16 -> global, tf32 -> smem)
    size_t obase = (size_t)blk * (32*256);
    for (int e = tid*4; e < 32*256; e += 1024) {
        int r = e >> 8, d = e & 255;
        float rk = rnk[r], rq = rnq[r];
        float4 kv = *(float4*)&Kt[r*PSTR + d];
        kv.x *= rk; kv.y *= rk; kv.z *= rk; kv.w *= rk;
        unsigned* kd = (unsigned*)&Kt[r*PSTR + d];
        kd[0]=f2tf(kv.x); kd[1]=f2tf(kv.y); kd[2]=f2tf(kv.z); kd[3]=f2tf(kv.w);
        float4 qv = *(float4*)&Qt[r*PSTR + d];
        qv.x *= rq; qv.y *= rq; qv.z *= rq; qv.w *= rq;
        __half2 qh0 = __floats2half2_rn(qv.x, qv.y);
        __half2 qh1 = __floats2half2_rn(qv.z, qv.w);
        uint2 qo = {*(unsigned*)&qh0, *(unsigned*)&qh1};
        *(uint2*)&g_qn_h[obase + e] = qo;
        unsigned* qd = (unsigned*)&Qt[r*PSTR + d];
        qd[0]=f2tf(qv.x); qd[1]=f2tf(qv.y); qd[2]=f2tf(qv.z); qd[3]=f2tf(qv.w);
    }
    __syncthreads();

    // 3b. write kn transposed [dv][time] as fp16 (Kt holds tf32-bit floats)
    for (int e = tid*2; e < 32*256; e += 512) {
        int r = e & 31, d = e >> 5;          // r even
        float v0 = Kt[r*PSTR + d];
        float v1 = Kt[(r+1)*PSTR + d];
        *(__half2*)&g_knT_h[obase + e] = __floats2half2_rn(v0, v1);
    }

    // 4. fused mma: Afull = kn@kn^T, attnF = qn@kn^T  (32x32, K=256)
    {
        int m0 = (wid >> 2) * 16, n0 = (wid & 3) * 8;
        const unsigned* Ku = (const unsigned*)Kt;
        const unsigned* Qu = (const unsigned*)Qt;
        float accA[4] = {0,0,0,0}, accQ[4] = {0,0,0,0};
#pragma unroll 4
        for (int kb = 0; kb < 256; kb += 8) {
            unsigned ak[4], aq[4], bf[2];
            ak[0] = Ku[(m0+lr)*PSTR + kb+lk];
            ak[1] = Ku[(m0+lr+8)*PSTR + kb+lk];
            ak[2] = Ku[(m0+lr)*PSTR + kb+lk+4];
            ak[3] = Ku[(m0+lr+8)*PSTR + kb+lk+4];
            aq[0] = Qu[(m0+lr)*PSTR + kb+lk];
            aq[1] = Qu[(m0+lr+8)*PSTR + kb+lk];
            aq[2] = Qu[(m0+lr)*PSTR + kb+lk+4];
            aq[3] = Qu[(m0+lr+8)*PSTR + kb+lk+4];
            bf[0] = Ku[(n0+lr)*PSTR + kb+lk];
            bf[1] = Ku[(n0+lr)*PSTR + kb+lk+4];
            mma_tf32(accA, ak, bf);
            mma_tf32(accQ, aq, bf);
        }
        size_t abase = (size_t)blk * 1024;
        int r0 = m0 + lr, r1 = r0 + 8, c0 = n0 + 2*lk, c1 = c0 + 1;
        float q00 = (c0 <= r0) ? accQ[0] : 0.f;
        float q01 = (c1 <= r0) ? accQ[1] : 0.f;
        float q10 = (c0 <= r1) ? accQ[2] : 0.f;
        float q11 = (c1 <= r1) ? accQ[3] : 0.f;
        *(__half2*)&g_attn_h[abase + r0*32 + c0] = __floats2half2_rn(q00, q01);
        *(__half2*)&g_attn_h[abase + r1*32 + c0] = __floats2half2_rn(q10, q11);
        Am[r0*33 + c0] = (c0 < r0) ? -bet[r0]*accA[0] : 0.f;
        Am[r0*33 + c1] = (c1 < r0) ? -bet[r0]*accA[1] : 0.f;
        Am[r1*33 + c0] = (c0 < r1) ? -bet[r1]*accA[2] : 0.f;
        Am[r1*33 + c1] = (c1 < r1) ? -bet[r1]*accA[3] : 0.f;
    }
    __syncthreads();

    // 5. iterative inversion (warp 0), then T' = (A+I)*diag(beta) as tf32
    if (tid < 32) {
        int ln = tid;
        for (int i = 1; i < 32; i++) {
            float t = 0.f;
            if (ln < i) for (int p = 0; p < i; p++) t += Am[i*33 + p] * Am[p*33 + ln];
            __syncwarp();
            if (ln < i) Am[i*33 + ln] += t;
            __syncwarp();
        }
    }
    __syncthreads();
    for (int e = tid; e < 1024; e += 256) {
        int i = e >> 5, j = e & 31;
        float t = Am[i*33 + j] + (i == j ? 1.f : 0.f);
        Ttf[i*36 + j] = f2tf(t * bet[j]);
    }
    // 6. load raw v tile (fp16) as tf32 into Qt (reuse)
    __syncthreads();
    for (int e = tid*4; e < 32*256; e += 1024) {
        int r = e >> 8, d = e & 255;
        uint2 vh = *(const uint2*)&g_vc_h[((size_t)(b*LL + l0 + r))*DD + h*DV + d];
        float2 va = __half22float2(*(__half2*)&vh.x);
        float2 vb2 = __half22float2(*(__half2*)&vh.y);
        unsigned* qd = (unsigned*)&Qt[r*PSTR + d];
        qd[0]=f2tf(va.x); qd[1]=f2tf(va.y); qd[2]=f2tf(vb2.x); qd[3]=f2tf(vb2.y);
    }
    __syncthreads();

    // 7. u = T'@v, w = T'@kn   (32x256, K=32) — fp16 outputs
    {
        int m0 = (wid & 1) * 16;
        int nb = (wid >> 1) * 64;
        const unsigned* Ku = (const unsigned*)Kt;
        const unsigned* Vu = (const unsigned*)Qt;
        unsigned a[4][4];
#pragma unroll
        for (int kk = 0; kk < 4; kk++) {
            int kb = kk*8;
            a[kk][0] = Ttf[(m0+lr)*36 + kb+lk];
            a[kk][1] = Ttf[(m0+lr+8)*36 + kb+lk];
            a[kk][2] = Ttf[(m0+lr)*36 + kb+lk+4];
            a[kk][3] = Ttf[(m0+lr+8)*36 + kb+lk+4];
        }
#pragma unroll
        for (int nt = 0; nt < 8; nt++) {
            int n0 = nb + nt*8;
            float au[4] = {0,0,0,0}, aw[4] = {0,0,0,0};
#pragma unroll
            for (int kk = 0; kk < 4; kk++) {
                int kb = kk*8;
                unsigned bu[2], bw[2];
                bu[0] = Vu[(kb+lk)*PSTR + n0+lr];
                bu[1] = Vu[(kb+lk+4)*PSTR + n0+lr];
                bw[0] = Ku[(kb+lk)*PSTR + n0+lr];
                bw[1] = Ku[(kb+lk+4)*PSTR + n0+lr];
                mma_tf32(au, a[kk], bu);
                mma_tf32(aw, a[kk], bw);
            }
            int r0 = m0 + lr, r1 = r0 + 8, cc = n0 + 2*lk;
            *(__half2*)&g_u_h[obase + r0*256 + cc] = __floats2half2_rn(au[0], au[1]);
            *(__half2*)&g_u_h[obase + r1*256 + cc] = __floats2half2_rn(au[2], au[3]);
            *(__half2*)&g_w_h[obase + r0*256 + cc] = __floats2half2_rn(aw[0], aw[1]);
            *(__half2*)&g_w_h[obase + r1*256 + cc] = __floats2half2_rn(aw[2], aw[3]);
        }
    }
}

// --------------- sequential inter-chunk scan (fp16 tensor-core mma) ---------
#define SFW 40
#define SCAN_SMEM 88576
__global__ __launch_bounds__(256) void scan_kernel()
{
    extern __shared__ char ssm[];
    float*    Sf  = (float*)ssm;                      // [256][40] f32
    unsigned* Sh  = (unsigned*)(ssm + 40960);         // [32][132] words
    unsigned* Tw  = (unsigned*)(ssm + 57856);         // tile (max 20480B)
    float*    Ui  = (float*)(ssm + 78336);            // [32][40] f32
    unsigned* Uh  = (unsigned*)(ssm + 83456);         // [32][20] words
    unsigned* Ah  = (unsigned*)(ssm + 86016);         // [32][20] words
    __half*   ShH = (__half*)Sh;
    __half*   UhH = (__half*)Uh;
    __half*   TwH = (__half*)Tw;

    int blk = blockIdx.x;
    int g  = blk & (NG-1);
    int bh = blk >> 3;
    int b  = bh >> 2;
    int h  = bh & 3;
    int tid = threadIdx.x;
    int wid = tid >> 5, lane = tid & 31;
    int lr = lane >> 2, lk = lane & 3;
    int m0 = (wid >> 2) * 16;
    int n0 = (wid & 3) * 8;

    for (int e = tid; e < 256*SFW; e += 256) Sf[e] = 0.f;
    for (int e = tid; e < 32*132; e += 256) Sh[e] = 0u;
    __syncthreads();

    for (int c = 0; c < NC; c++) {
        size_t base = ((size_t)bh*NC + c) * (32*256);
        size_t abase = ((size_t)bh*NC + c) * 1024;

        for (int e = tid*2; e < 1024; e += 512) {
            int r = e >> 5, j = e & 31;
            unsigned uw = *(const unsigned*)&g_u_h[base + r*256 + g*32 + j];
            float2 uf = __half22float2(*(__half2*)&uw);
            Ui[r*SFW + j] = uf.x; Ui[r*SFW + j + 1] = uf.y;
        }
        {
            int e = tid*4;
            int r = e >> 5, j = e & 31;
            *(uint2*)&Ah[r*20 + (j >> 1)] = *(const uint2*)&g_attn_h[abase + e];
        }
        for (int e = tid*8; e < 8192; e += 2048) {
            int r = e >> 8, jj = e & 255;
            *(uint4*)&TwH[r*264 + jj] = *(const uint4*)&g_w_h[base + e];
        }
        __syncthreads();

        // (1) u_i = u - w@S    (32x32, K=256, fp16)
        {
            float acc[4] = {0.f, 0.f, 0.f, 0.f};
#pragma unroll 4
            for (int kb = 0; kb < 256; kb += 16) {
                int kw = (kb >> 1) + lk;
                unsigned a[4], bf[2];
                a[0] = Tw[(m0+lr)*132 + kw];
                a[1] = Tw[(m0+lr+8)*132 + kw];
                a[2] = Tw[(m0+lr)*132 + kw + 4];
                a[3] = Tw[(m0+lr+8)*132 + kw + 4];
                bf[0] = Sh[(n0+lr)*132 + kw];
                bf[1] = Sh[(n0+lr)*132 + kw + 4];
                mma_f16(acc, a, bf);
            }
            int r0 = m0 + lr, r1 = r0 + 8, cb = n0 + 2*lk;
            float u0 = Ui[r0*SFW+cb]   - acc[0];
            float u1 = Ui[r0*SFW+cb+1] - acc[1];
            float u2 = Ui[r1*SFW+cb]   - acc[2];
            float u3 = Ui[r1*SFW+cb+1] - acc[3];
            UhH[cb*40 + r0]     = __float2half_rn(u0);
            UhH[(cb+1)*40 + r0] = __float2half_rn(u1);
            UhH[cb*40 + r1]     = __float2half_rn(u2);
            UhH[(cb+1)*40 + r1] = __float2half_rn(u3);
        }
        __syncthreads();

        for (int e = tid*8; e < 8192; e += 2048) {
            int r = e >> 8, jj = e & 255;
            *(uint4*)&TwH[r*264 + jj] = *(const uint4*)&g_qn_h[base + e];
        }
        __syncthreads();

        // (2) o = q@S + attn@u_i  -> g_delta (fp16)
        {
            float acc[4] = {0.f, 0.f, 0.f, 0.f};
#pragma unroll 4
            for (int kb = 0; kb < 256; kb += 16) {
                int kw = (kb >> 1) + lk;
                unsigned a[4], bf[2];
                a[0] = Tw[(m0+lr)*132 + kw];
                a[1] = Tw[(m0+lr+8)*132 + kw];
                a[2] = Tw[(m0+lr)*132 + kw + 4];
                a[3] = Tw[(m0+lr+8)*132 + kw + 4];
                bf[0] = Sh[(n0+lr)*132 + kw];
                bf[1] = Sh[(n0+lr)*132 + kw + 4];
                mma_f16(acc, a, bf);
            }
#pragma unroll
            for (int kb = 0; kb < 32; kb += 16) {
                int kw = (kb >> 1) + lk;
                unsigned a[4], bf[2];
                a[0] = Ah[(m0+lr)*20 + kw];
                a[1] = Ah[(m0+lr+8)*20 + kw];
                a[2] = Ah[(m0+lr)*20 + kw + 4];
                a[3] = Ah[(m0+lr+8)*20 + kw + 4];
                bf[0] = Uh[(n0+lr)*20 + kw];
                bf[1] = Uh[(n0+lr)*20 + kw + 4];
                mma_f16(acc, a, bf);
            }
            size_t ob = ((size_t)(b*LL + c*32 + m0 + lr))*DD + h*DV + g*32 + n0 + 2*lk;
            *(__half2*)&g_delta_h[ob]        = __floats2half2_rn(acc[0], acc[1]);
            *(__half2*)&g_delta_h[ob + 8*DD] = __floats2half2_rn(acc[2], acc[3]);
        }
        __syncthreads();

        for (int e = tid*8; e < 8192; e += 2048) {
            int r = e >> 5, jj = e & 31;
            *(uint4*)&TwH[r*40 + jj] = *(const uint4*)&g_knT_h[base + e];
        }
        __syncthreads();

        // (3) S += k^T @ u_i
#pragma unroll
        for (int t = 0; t < 2; t++) {
            int tm = (wid*2 + t) * 16;
#pragma unroll
            for (int tn = 0; tn < 4; tn++) {
                int nn = tn*8;
                int r0 = tm + lr, r1 = r0 + 8, cb = nn + 2*lk;
                float acc[4];
                acc[0] = Sf[r0*SFW+cb]; acc[1] = Sf[r0*SFW+cb+1];
                acc[2] = Sf[r1*SFW+cb]; acc[3] = Sf[r1*SFW+cb+1];
#pragma unroll
                for (int kb = 0; kb < 32; kb += 16) {
                    int kw = (kb >> 1) + lk;
                    unsigned a[4], bf[2];
                    a[0] = Tw[(tm+lr)*20 + kw];
                    a[1] = Tw[(tm+lr+8)*20 + kw];
                    a[2] = Tw[(tm+lr)*20 + kw + 4];
                    a[3] = Tw[(tm+lr+8)*20 + kw + 4];
                    bf[0] = Uh[(nn+lr)*20 + kw];
                    bf[1] = Uh[(nn+lr)*20 + kw + 4];
                    mma_f16(acc, a, bf);
                }
                Sf[r0*SFW+cb] = acc[0]; Sf[r0*SFW+cb+1] = acc[1];
                Sf[r1*SFW+cb] = acc[2]; Sf[r1*SFW+cb+1] = acc[3];
                ShH[cb*264 + r0]     = __float2half_rn(acc[0]);
                ShH[(cb+1)*264 + r0] = __float2half_rn(acc[1]);
                ShH[cb*264 + r1]     = __float2half_rn(acc[2]);
                ShH[(cb+1)*264 + r1] = __float2half_rn(acc[3]);
            }
        }
        __syncthreads();
    }
}

// ------------------- per-(head,channel) FIR conv (fp16 io) ------------------
template<int K>
__global__ __launch_bounds__(256) void fir_kernel(
    const float* __restrict__ fw, __half* __restrict__ y)
{
    __shared__ float2 vbuf[(128 + K - 1) * 16];
    __shared__ float2 wbuf[16 * K];
    int bh = blockIdx.x;
    int b = bh / HH, h = bh % HH;
    int l0 = blockIdx.y * 128;
    int d0 = blockIdx.z * 32;
    int tid = threadIdx.x;

    for (int idx = tid; idx < 16*K; idx += 256) {
        int dp = idx / K, t = idx % K;
        float2 wv;
        wv.x = fw[(size_t)(h*DV + d0 + 2*dp)*K + t];
        wv.y = fw[(size_t)(h*DV + d0 + 2*dp + 1)*K + t];
        wbuf[dp*K + t] = wv;
    }
    for (int idx = tid; idx < (128 + K - 1)*16; idx += 256) {
        int lrr = idx >> 4, dp = idx & 15;
        int l = l0 - (K - 1) + lrr;
        vbuf[idx] = (l >= 0)
            ? __half22float2(*(const __half2*)&g_vc_h[((size_t)(b*LL + l))*DD + h*DV + d0 + 2*dp])
            : make_float2(0.f, 0.f);
    }
    __syncthreads();

    int dp = tid & 15;
    int lr0 = (tid >> 4) * 8;
    for (int m = 0; m < 8; m++) {
        int lrr = lr0 + m;
        float2 acc = {0.f, 0.f};
#pragma unroll
        for (int t = 0; t < K; t++) {
            float2 v = vbuf[(lrr + t)*16 + dp];
            float2 wv = wbuf[dp*K + t];
            acc.x = fmaf(v.x, wv.x, acc.x);
            acc.y = fmaf(v.y, wv.y, acc.y);
        }
        *(__half2*)&y[((size_t)(b*LL + l0 + lrr))*DD + h*DV + d0 + 2*dp]
            = __floats2half2_rn(acc.x, acc.y);
    }
}

// ------------- gate input assembly (hs + stats), stored as fp16 -------------
__global__ __launch_bounds__(256) void stats_kernel(const float* __restrict__ hs)
{
    int n = blockIdx.x, tid = threadIdx.x;
    {
        int i = tid * 4;
        float4 v = *(const float4*)&hs[(size_t)n*DD + i];
        __half2 lo = __floats2half2_rn(v.x, v.y);
        __half2 hi = __floats2half2_rn(v.z, v.w);
        uint2 o = {*(unsigned*)&lo, *(unsigned*)&hi};
        *(uint2*)&g_gatein_h[(size_t)n*GINP + i] = o;
    }
    if (tid < 32) g_gatein_h[(size_t)n*GINP + GIN + tid] = __float2half_rn(0.f);
    int warp = tid >> 5, lane = tid & 31;
    for (int rep = 0; rep < 2; rep++) {
        int combo = warp*2 + rep;
        int path = combo >> 2, h = combo & 3;
        const __half* p;
        if      (path == 0) p = g_short_h;
        else if (path == 1) p = g_long_h;
        else if (path == 2) p = g_delta_h;
        else                p = g_vc_h;
        p += (size_t)n*DD + h*DV;
        float s1 = 0.f, s2 = 0.f;
        for (int j = lane; j < 256; j += 32) {
            float x = __half2float(p[j]); s1 += x; s2 += x*x;
        }
#pragma unroll
        for (int st = 16; st > 0; st >>= 1) {
            s1 += __shfl_down_sync(0xffffffffu, s1, st);
            s2 += __shfl_down_sync(0xffffffffu, s2, st);
        }
        if (lane == 0) {
            float m  = s1 * (1.f/256.f);
            float va = s2 * (1.f/256.f) - m*m;
            g_gatein_h[(size_t)n*GINP + DD + path*8 + h*2]     = __float2half_rn(m);
            g_gatein_h[(size_t)n*GINP + DD + path*8 + h*2 + 1] = __float2half_rn(va);
        }
    }
}

// ------------------------- gate2 + softmax + floor --------------------------
__global__ __launch_bounds__(256) void gate2_kernel(
    const float* __restrict__ w2, const float* __restrict__ log_temp,
    const float* __restrict__ base_bias, const float* __restrict__ floor_raw)
{
    __shared__ float hrow[HID];
    __shared__ float lg[16];
    int n = blockIdx.x, tid = threadIdx.x;
    for (int i = tid; i < HID; i += 256) hrow[i] = g_hmid[(size_t)n*HID + i];
    __syncthreads();
    int warp = tid >> 5, lane = tid & 31;
    for (int rep = 0; rep < 2; rep++) {
        int o = warp*2 + rep;
        const float* wr = w2 + (size_t)o*HID;
        float s = 0.f;
        for (int i = lane; i < HID; i += 32) s = fmaf(hrow[i], wr[i], s);
#pragma unroll
        for (int st = 16; st > 0; st >>= 1) s += __shfl_down_sync(0xffffffffu, s, st);
        if (lane == 0) lg[o] = s;
    }
    __syncthreads();
    if (tid < 4) {
        int h = tid;
        float temp = log1pf(expf(log_temp[h])) + 1e-4f;
        float z[4], m = -1e30f;
#pragma unroll
        for (int i = 0; i < 4; i++) {
            z[i] = (lg[h*4+i] + base_bias[h*4+i]) / temp;
            m = fmaxf(m, z[i]);
        }
        float e[4], s = 0.f;
#pragma unroll
        for (int i = 0; i < 4; i++) { e[i] = expf(z[i] - m); s += e[i]; }
        float p[4], s2 = 0.f;
#pragma unroll
        for (int i = 0; i < 4; i++) {
            p[i] = e[i] / s;
            float f = 0.05f / (1.f + expf(-floor_raw[h*4+i]));
            p[i] = fmaxf(p[i], f);
            s2 += p[i];
        }
#pragma unroll
        for (int i = 0; i < 4; i++) g_probs[(size_t)n*16 + h*4 + i] = p[i] / s2;
    }
}

// ------------- path mix + RMS norm, output stored as fp16 -------------------
__global__ __launch_bounds__(256) void mix_kernel(const float* __restrict__ onorm)
{
    __shared__ float pr[16];
    __shared__ float wsum[8];
    int n = blockIdx.x, tid = threadIdx.x;
    if (tid < 16) pr[tid] = g_probs[(size_t)n*16 + tid];
    __syncthreads();
    int h = tid >> 6;
    int dd = (tid & 63) * 4;
    size_t pb = (size_t)n*DD + h*DV + dd;
    uint2 sraw = *(const uint2*)&g_short_h[pb];
    uint2 lraw = *(const uint2*)&g_long_h[pb];
    uint2 draw = *(const uint2*)&g_delta_h[pb];
    uint2 vraw = *(const uint2*)&g_vc_h[pb];
    float2 sa = __half22float2(*(__half2*)&sraw.x), sb = __half22float2(*(__half2*)&sraw.y);
    float2 la = __half22float2(*(__half2*)&lraw.x), lb = __half22float2(*(__half2*)&lraw.y);
    float2 da = __half22float2(*(__half2*)&draw.x), db = __half22float2(*(__half2*)&draw.y);
    float2 va = __half22float2(*(__half2*)&vraw.x), vb = __half22float2(*(__half2*)&vraw.y);
    float p0 = pr[h*4+0], p1 = pr[h*4+1], p2 = pr[h*4+2], p3 = pr[h*4+3];
    float o[4];
    o[0] = p0*sa.x + p1*la.x + p2*da.x + p3*va.x;
    o[1] = p0*sa.y + p1*la.y + p2*da.y + p3*va.y;
    o[2] = p0*sb.x + p1*lb.x + p2*db.x + p3*vb.x;
    o[3] = p0*sb.y + p1*lb.y + p2*db.y + p3*vb.y;
    float ss = o[0]*o[0] + o[1]*o[1] + o[2]*o[2] + o[3]*o[3];
#pragma unroll
    for (int st = 16; st > 0; st >>= 1) ss += __shfl_down_sync(0xffffffffu, ss, st);
    int warp = tid >> 5, lane = tid & 31;
    if (lane == 0) wsum[warp] = ss;
    __syncthreads();
    float tot = wsum[h*2] + wsum[h*2+1];
    float scale = rsqrtf(tot * (1.f/256.f) + 1e-5f);
    __half2 h0 = __floats2half2_rn(o[0]*scale*onorm[dd],   o[1]*scale*onorm[dd+1]);
    __half2 h1 = __floats2half2_rn(o[2]*scale*onorm[dd+2], o[3]*scale*onorm[dd+3]);
    uint2 pk = {*(unsigned*)&h0, *(unsigned*)&h1};
    *(uint2*)&g_mix_h[pb] = pk;
}

// ------------------------- launch ------------------------------------------
extern "C" void kernel_launch(void* const* d_in, const int* in_sizes, int n_in,
                              void* d_out, int out_size)
{
    const float* hs        = (const float*)d_in[0];
    const float* Wq        = (const float*)d_in[1];
    const float* Wk        = (const float*)d_in[2];
    const float* Wv        = (const float*)d_in[3];
    const float* Wb        = (const float*)d_in[4];
    const float* qconv_w   = (const float*)d_in[5];
    const float* kconv_w   = (const float*)d_in[6];
    const float* vconv_w   = (const float*)d_in[7];
    const float* fir_s     = (const float*)d_in[8];
    const float* fir_l     = (const float*)d_in[9];
    const float* gate_w1   = (const float*)d_in[10];
    const float* gate_b1   = (const float*)d_in[11];
    const float* gate_w2   = (const float*)d_in[12];
    const float* log_temp  = (const float*)d_in[13];
    const float* base_bias = (const float*)d_in[14];
    const float* floor_raw = (const float*)d_in[15];
    const float* onorm_w   = (const float*)d_in[16];
    const float* Wo        = (const float*)d_in[17];
    float* out = (float*)d_out;

    void *p_qlin, *p_klin, *p_vlin, *p_qc, *p_kc, *p_vc, *p_hmid, *p_short, *p_long;
    void *p_hsh, *p_wqh, *p_wkh, *p_wvh, *p_woh, *p_gw1h, *p_gateinh, *p_mixh;
    cudaGetSymbolAddress(&p_qlin, g_qlin_h);
    cudaGetSymbolAddress(&p_klin, g_klin_h);
    cudaGetSymbolAddress(&p_vlin, g_vlin_h);
    cudaGetSymbolAddress(&p_qc, g_qc_h);
    cudaGetSymbolAddress(&p_kc, g_kc_h);
    cudaGetSymbolAddress(&p_vc, g_vc_h);
    cudaGetSymbolAddress(&p_hmid, g_hmid);
    cudaGetSymbolAddress(&p_short, g_short_h);
    cudaGetSymbolAddress(&p_long, g_long_h);
    cudaGetSymbolAddress(&p_hsh, g_hs_h);
    cudaGetSymbolAddress(&p_wqh, g_wq_h);
    cudaGetSymbolAddress(&p_wkh, g_wk_h);
    cudaGetSymbolAddress(&p_wvh, g_wv_h);
    cudaGetSymbolAddress(&p_woh, g_wo_h);
    cudaGetSymbolAddress(&p_gw1h, g_gw1_h);
    cudaGetSymbolAddress(&p_gateinh, g_gatein_h);
    cudaGetSymbolAddress(&p_mixh, g_mix_h);

    cudaFuncSetAttribute(scan_kernel,
        cudaFuncAttributeMaxDynamicSharedMemorySize, SCAN_SMEM);
    cudaFuncSetAttribute(precompute_kernel,
        cudaFuncAttributeMaxDynamicSharedMemorySize, PSMEM);
    cudaFuncSetAttribute(hgemm,
        cudaFuncAttributeMaxDynamicSharedMemorySize, HGEMM_SMEM);

    dim3 blk(256);

    // 0. pre-convert hs + weights to fp16 (gate_w1 padded separately)
    cvt_h6<<<dim3(NROW*DD/1024, 6), blk>>>(
        hs, (__half*)p_hsh, NROW*DD,
        Wq, (__half*)p_wqh, DD*DD,
        Wk, (__half*)p_wkh, DD*DD,
        Wv, (__half*)p_wvh, DD*DD,
        Wo, (__half*)p_woh, DD*DD,
        nullptr, nullptr, 0);
    cvt_gw1pad<<<(HID*GINP/4 + 255)/256, blk>>>(gate_w1);

    // q/k/v projections — fp16 outputs (mode 2)
    hgemm<<<dim3(DD/128, NROW/128, 3), blk, HGEMM_SMEM>>>(
        (const __half*)p_hsh,
        (const __half*)p_wqh, (const __half*)p_wkh, (const __half*)p_wvh,
        (float*)p_qlin, (float*)p_klin, (float*)p_vlin,
        nullptr, NROW, DD, DD, 2);

    // causal conv4 + SiLU (fp16 io, 4 elems/thread)
    conv4_silu3<<<dim3(NROW*DD/1024, 3), blk>>>(
        (const __half*)p_qlin, (const __half*)p_klin, (const __half*)p_vlin,
        qconv_w, kconv_w, vconv_w,
        (__half*)p_qc, (__half*)p_kc, (__half*)p_vc);

    // beta
    beta_kernel<<<NROW, 128>>>(hs, Wb);

    // delta-rule
    precompute_kernel<<<BB*HH*NC, blk, PSMEM>>>();
    scan_kernel<<<BB*HH*NG, blk, SCAN_SMEM>>>();

    // FIR paths
    fir_kernel<3><<<dim3(BB*HH, LL/128, DV/32), blk>>>(fir_s, (__half*)p_short);
    fir_kernel<63><<<dim3(BB*HH, LL/128, DV/32), blk>>>(fir_l, (__half*)p_long);

    // gate
    stats_kernel<<<NROW, blk>>>(hs);
    hgemm<<<dim3(HID/128, NROW/128, 1), blk, HGEMM_SMEM>>>(
        (const __half*)p_gateinh,
        (const __half*)p_gw1h, nullptr, nullptr,
        (float*)p_hmid, nullptr, nullptr,
        gate_b1, NROW, HID, GINP, 1);
    gate2_kernel<<<NROW, blk>>>(gate_w2, log_temp, base_bias, floor_raw);

    // mix + RMS norm
    mix_kernel<<<NROW, blk>>>(onorm_w);

    // output projection (fp32 out)
    hgemm<<<dim3(DD/128, NROW/128, 1), blk, HGEMM_SMEM>>>(
        (const __half*)p_mixh,
        (const __half*)p_woh, nullptr, nullptr,
        out, nullptr, nullptr,
        nullptr, NROW, DD, DD, 0);
}

// round 15
// speedup vs baseline: 1.0264x; 1.0264x over previous
#include <cuda_runtime.h>
#include <cuda_fp16.h>
#include <math.h>
#include <stdint.h>

#define BB 2
#define LL 2048
#define DD 1024
#define HH 4
#define DV 256
#define CKN 32
#define NC 64              // LL / CKN
#define NROW (BB*LL)       // 4096
#define GIN 1056
#define GINP 1088          // padded to multiple of 64
#define HID 2048
#define NG 8               // Dv groups of 32 in the scan

// ------------------------- scratch (device globals) -------------------------
__device__ float g_beta[NROW*HH];
__device__ float g_probs[NROW*16];
// fp16 intermediates + GEMM operands
__device__ __half g_qn_h[NROW*DD];       // [bh][c][time32][dv256]
__device__ __half g_knT_h[NROW*DD];      // [bh][c][dv256][time32]
__device__ __half g_u_h[NROW*DD];        // [bh][c][time32][dv256]
__device__ __half g_w_h[NROW*DD];        // [bh][c][time32][dv256]
__device__ __half g_attn_h[BB*HH*NC*CKN*CKN];
__device__ __half g_delta_h[NROW*DD];
__device__ __half g_short_h[NROW*DD];
__device__ __half g_long_h[NROW*DD];
__device__ __half g_hmid_h[NROW*HID];
__device__ __half g_qlin_h[NROW*DD];
__device__ __half g_klin_h[NROW*DD];
__device__ __half g_vlin_h[NROW*DD];
__device__ __half g_qc_h[NROW*DD];
__device__ __half g_kc_h[NROW*DD];
__device__ __half g_vc_h[NROW*DD];
__device__ __half g_hs_h[NROW*DD];
__device__ __half g_wq_h[DD*DD];
__device__ __half g_wk_h[DD*DD];
__device__ __half g_wv_h[DD*DD];
__device__ __half g_wo_h[DD*DD];
__device__ __half g_gw1_h[HID*GINP];
__device__ __half g_gatein_h[NROW*GINP];
__device__ __half g_mix_h[NROW*DD];

// ------------------------- helpers ------------------------------------------
__device__ __forceinline__ unsigned f2tf(float x) {
    unsigned r;
    asm("cvt.rna.tf32.f32 %0, %1;" : "=r"(r) : "f"(x));
    return r;
}

__device__ __forceinline__ void mma_tf32(float* c, const unsigned* a, const unsigned* b) {
    asm volatile(
        "mma.sync.aligned.m16n8k8.row.col.f32.tf32.tf32.f32 "
        "{%0,%1,%2,%3}, {%4,%5,%6,%7}, {%8,%9}, {%0,%1,%2,%3};"
        : "+f"(c[0]), "+f"(c[1]), "+f"(c[2]), "+f"(c[3])
        : "r"(a[0]), "r"(a[1]), "r"(a[2]), "r"(a[3]), "r"(b[0]), "r"(b[1]));
}

__device__ __forceinline__ void mma_f16(float* c, const unsigned* a, const unsigned* b) {
    asm volatile(
        "mma.sync.aligned.m16n8k16.row.col.f32.f16.f16.f32 "
        "{%0,%1,%2,%3}, {%4,%5,%6,%7}, {%8,%9}, {%0,%1,%2,%3};"
        : "+f"(c[0]), "+f"(c[1]), "+f"(c[2]), "+f"(c[3])
        : "r"(a[0]), "r"(a[1]), "r"(a[2]), "r"(a[3]), "r"(b[0]), "r"(b[1]));
}

#define LDSM4(r, addr)                                                        \
    asm volatile("ldmatrix.sync.aligned.m8n8.x4.shared.b16 {%0,%1,%2,%3}, [%4];" \
        : "=r"((r)[0]), "=r"((r)[1]), "=r"((r)[2]), "=r"((r)[3]) : "r"(addr))

// ------------------------- bulk fp32 -> fp16 conversion ---------------------
__global__ __launch_bounds__(256) void cvt_h6(
    const float* __restrict__ s0, __half* __restrict__ d0, int n0,
    const float* __restrict__ s1, __half* __restrict__ d1, int n1,
    const float* __restrict__ s2, __half* __restrict__ d2, int n2,
    const float* __restrict__ s3, __half* __restrict__ d3, int n3,
    const float* __restrict__ s4, __half* __restrict__ d4, int n4,
    const float* __restrict__ s5, __half* __restrict__ d5, int n5)
{
    const float* s; __half* d; int n;
    switch (blockIdx.y) {
        case 0: s=s0; d=d0; n=n0; break;
        case 1: s=s1; d=d1; n=n1; break;
        case 2: s=s2; d=d2; n=n2; break;
        case 3: s=s3; d=d3; n=n3; break;
        case 4: s=s4; d=d4; n=n4; break;
        default: s=s5; d=d5; n=n5; break;
    }
    int i = (blockIdx.x * 256 + threadIdx.x) * 4;
    if (i < n) {
        float4 v = *(const float4*)(s + i);
        __half2 lo = __floats2half2_rn(v.x, v.y);
        __half2 hi = __floats2half2_rn(v.z, v.w);
        uint2 o = {*(unsigned*)&lo, *(unsigned*)&hi};
        *(uint2*)(d + i) = o;
    }
}

// --------- gate_w1 fp32[HID][GIN] -> fp16[HID][GINP] with zero pad ----------
__global__ __launch_bounds__(256) void cvt_gw1pad(const float* __restrict__ src)
{
    int i = (blockIdx.x * 256 + threadIdx.x) * 4;
    if (i >= HID*GINP) return;
    int row = i / GINP, col = i % GINP;
    float4 v;
    if (col < GIN) v = *(const float4*)&src[(size_t)row*GIN + col];
    else v = make_float4(0.f, 0.f, 0.f, 0.f);
    __half2 lo = __floats2half2_rn(v.x, v.y);
    __half2 hi = __floats2half2_rn(v.z, v.w);
    uint2 o = {*(unsigned*)&lo, *(unsigned*)&hi};
    *(uint2*)&g_gw1_h[i] = o;
}

// ---------------- fp16 tensor GEMM: C = A(MxK) @ B(NxK)^T -------------------
// K=64 per stage, 2-stage cp.async pipeline, 128x128 tile, ldmatrix frags.
// Smem rows: 64 halves @ 144B stride (LDSM conflict-free).
// mode bit0: +bias, exact GELU.  mode bit1: fp16 out.
#define HSTRB 144
#define HSTAGE_BYTES (128*HSTRB)        // 18432
#define HGEMM_SMEM (4*HSTAGE_BYTES)     // 73728

#define HLOAD64(kt, st) do {                                                   \
    const __half* Ap_ = A + (size_t)bm*K + (kt)*64;                            \
    const __half* Bp_ = B + (size_t)bn*K + (kt)*64;                            \
    _Pragma("unroll")                                                          \
    for (int i_ = 0; i_ < 4; i_++) {                                           \
        int e_ = tid + i_*256;                                                 \
        int row_ = e_ >> 3, seg_ = e_ & 7;                                     \
        unsigned doff_ = (unsigned)row_*HSTRB + (unsigned)seg_*16;             \
        asm volatile("cp.async.cg.shared.global [%0], [%1], 16;"               \
            :: "r"(smb + (unsigned)((st)*HSTAGE_BYTES) + doff_),               \
               "l"(Ap_ + (size_t)row_*K + seg_*8));                            \
        asm volatile("cp.async.cg.shared.global [%0], [%1], 16;"               \
            :: "r"(smb + (unsigned)(2*HSTAGE_BYTES + (st)*HSTAGE_BYTES) + doff_), \
               "l"(Bp_ + (size_t)row_*K + seg_*8));                            \
    }                                                                          \
} while (0)

__global__ __launch_bounds__(256, 2) void hgemm(
    const __half* __restrict__ A,
    const __half* __restrict__ Bm0, const __half* __restrict__ Bm1, const __half* __restrict__ Bm2,
    float* __restrict__ Cm0, float* __restrict__ Cm1, float* __restrict__ Cm2,
    const float* __restrict__ bias, int M, int N, int K, int mode)
{
    extern __shared__ char tsm[];

    const __half* B = (blockIdx.z == 0) ? Bm0 : (blockIdx.z == 1) ? Bm1 : Bm2;
    float*        C = (blockIdx.z == 0) ? Cm0 : (blockIdx.z == 1) ? Cm1 : Cm2;

    int tid = threadIdx.x;
    int bm = blockIdx.y * 128, bn = blockIdx.x * 128;
    unsigned smb;
    asm("{ .reg .u64 t; cvta.to.shared.u64 t, %1; cvt.u32.u64 %0, t; }"
        : "=r"(smb) : "l"(tsm));

    int wid = tid >> 5, lane = tid & 31;
    int wm = (wid >> 2) * 64, wn = (wid & 3) * 32;
    int lr = lane >> 2, lk = lane & 3;

    int a_row = (lane & 7) + ((lane >> 3) & 1) * 8;
    int a_kb  = (lane >> 4) * 16;
    int b_row = (lane & 7) + ((lane >> 4) & 1) * 8;
    int b_kb  = ((lane >> 3) & 1) * 16;

    float acc[4][4][4];
#pragma unroll
    for (int mi = 0; mi < 4; mi++)
#pragma unroll
        for (int ni = 0; ni < 4; ni++)
#pragma unroll
            for (int j = 0; j < 4; j++) acc[mi][ni][j] = 0.f;

    int niter = K >> 6;

    HLOAD64(0, 0);
    asm volatile("cp.async.commit_group;");

    for (int t = 0; t < niter; t++) {
        asm volatile("cp.async.wait_group 0;");
        __syncthreads();
        if (t + 1 < niter) {
            HLOAD64(t + 1, (t + 1) & 1);
            asm volatile("cp.async.commit_group;");
        }
        int cur = t & 1;
        unsigned a_base = smb + (unsigned)(cur*HSTAGE_BYTES);
        unsigned b_base = smb + (unsigned)(2*HSTAGE_BYTES + cur*HSTAGE_BYTES);
#pragma unroll
        for (int ks = 0; ks < 4; ks++) {
            unsigned af[4][4], bq[2][4];
#pragma unroll
            for (int mi = 0; mi < 4; mi++) {
                unsigned addr = a_base + (unsigned)((wm + mi*16 + a_row)*HSTRB + ks*32 + a_kb);
                LDSM4(af[mi], addr);
            }
#pragma unroll
            for (int nq = 0; nq < 2; nq++) {
                unsigned addr = b_base + (unsigned)((wn + nq*16 + b_row)*HSTRB + ks*32 + b_kb);
                LDSM4(bq[nq], addr);
            }
#pragma unroll
            for (int mi = 0; mi < 4; mi++)
#pragma unroll
                for (int ni = 0; ni < 4; ni++)
                    mma_f16(acc[mi][ni], af[mi], &bq[ni >> 1][(ni & 1) * 2]);
        }
        __syncthreads();
    }

#pragma unroll
    for (int mi = 0; mi < 4; mi++) {
        int r0 = bm + wm + mi*16 + lr;
#pragma unroll
        for (int ni = 0; ni < 4; ni++) {
            int c = bn + wn + ni*8 + 2*lk;
            float v[4] = {acc[mi][ni][0], acc[mi][ni][1], acc[mi][ni][2], acc[mi][ni][3]};
            if (mode & 1) {
                float b0 = bias[c], b1 = bias[c+1];
                v[0] += b0; v[1] += b1; v[2] += b0; v[3] += b1;
#pragma unroll
                for (int j = 0; j < 4; j++)
                    v[j] = 0.5f * v[j] * (1.f + erff(v[j] * 0.70710678118654752f));
            }
            if (mode & 2) {
                __half* Ch = (__half*)C;
                *(__half2*)&Ch[(size_t)r0*N + c]     = __floats2half2_rn(v[0], v[1]);
                *(__half2*)&Ch[(size_t)(r0+8)*N + c] = __floats2half2_rn(v[2], v[3]);
            } else {
                float2 lo = {v[0], v[1]};
                float2 hi = {v[2], v[3]};
                *(float2*)&C[(size_t)r0*N + c]       = lo;
                *(float2*)&C[(size_t)(r0+8)*N + c]   = hi;
            }
        }
    }
}

// ------------- depthwise causal conv4 + SiLU, fp16 io, 4 elems/thread -------
__global__ __launch_bounds__(256) void conv4_silu3(
    const __half* __restrict__ x0, const __half* __restrict__ x1, const __half* __restrict__ x2,
    const float* __restrict__ w0, const float* __restrict__ w1, const float* __restrict__ w2,
    __half* __restrict__ y0, __half* __restrict__ y1, __half* __restrict__ y2)
{
    const __half* x; const float* w; __half* y;
    if (blockIdx.y == 0)      { x = x0; w = w0; y = y0; }
    else if (blockIdx.y == 1) { x = x1; w = w1; y = y1; }
    else                      { x = x2; w = w2; y = y2; }
    int q = blockIdx.x * 256 + threadIdx.x;     // quad index over NROW*DD/4
    int dq = q & (DD/4 - 1);
    int l = (q >> 8) & (LL - 1);
    int d = dq * 4;
    float4 w0v = *(const float4*)(w + d*4);
    float4 w1v = *(const float4*)(w + d*4 + 4);
    float4 w2v = *(const float4*)(w + d*4 + 8);
    float4 w3v = *(const float4*)(w + d*4 + 12);
    const uint2* xp = (const uint2*)x + q;
    uint2 raw = xp[0];
    float2 xa = __half22float2(*(__half2*)&raw.x);
    float2 xb = __half22float2(*(__half2*)&raw.y);
    float a0 = w0v.w * xa.x, a1 = w1v.w * xa.y, a2 = w2v.w * xb.x, a3 = w3v.w * xb.y;
    if (l >= 1) {
        uint2 t = xp[-(DD/4)];
        float2 ta = __half22float2(*(__half2*)&t.x);
        float2 tb = __half22float2(*(__half2*)&t.y);
        a0 += w0v.z*ta.x; a1 += w1v.z*ta.y; a2 += w2v.z*tb.x; a3 += w3v.z*tb.y;
    }
    if (l >= 2) {
        uint2 t = xp[-(DD/2)];
        float2 ta = __half22float2(*(__half2*)&t.x);
        float2 tb = __half22float2(*(__half2*)&t.y);
        a0 += w0v.y*ta.x; a1 += w1v.y*ta.y; a2 += w2v.y*tb.x; a3 += w3v.y*tb.y;
    }
    if (l >= 3) {
        uint2 t = xp[-(3*DD/4)];
        float2 ta = __half22float2(*(__half2*)&t.x);
        float2 tb = __half22float2(*(__half2*)&t.y);
        a0 += w0v.x*ta.x; a1 += w1v.x*ta.y; a2 += w2v.x*tb.x; a3 += w3v.x*tb.y;
    }
    a0 = a0 / (1.f + __expf(-a0));
    a1 = a1 / (1.f + __expf(-a1));
    a2 = a2 / (1.f + __expf(-a2));
    a3 = a3 / (1.f + __expf(-a3));
    __half2 o0 = __floats2half2_rn(a0, a1);
    __half2 o1 = __floats2half2_rn(a2, a3);
    uint2 ov = {*(unsigned*)&o0, *(unsigned*)&o1};
    ((uint2*)y)[q] = ov;
}

// ------------------- beta = sigmoid(hs_h @ Wb^T) (fp16 hs) ------------------
__global__ __launch_bounds__(128) void beta_kernel(const float* __restrict__ Wb)
{
    __shared__ float red[4][128];
    int n = blockIdx.x, tid = threadIdx.x;
    const __half* hr = g_hs_h + (size_t)n * DD;
    float s0=0,s1=0,s2=0,s3=0;
    for (int i = tid*2; i < DD; i += 256) {
        float2 x = __half22float2(*(const __half2*)&hr[i]);
        s0 += x.x * Wb[i]        + x.y * Wb[i+1];
        s1 += x.x * Wb[DD + i]   + x.y * Wb[DD + i+1];
        s2 += x.x * Wb[2*DD + i] + x.y * Wb[2*DD + i+1];
        s3 += x.x * Wb[3*DD + i] + x.y * Wb[3*DD + i+1];
    }
    red[0][tid]=s0; red[1][tid]=s1; red[2][tid]=s2; red[3][tid]=s3;
    __syncthreads();
    for (int st = 64; st > 0; st >>= 1) {
        if (tid < st)
#pragma unroll
            for (int h = 0; h < 4; h++) red[h][tid] += red[h][tid + st];
        __syncthreads();
    }
    if (tid < 4) g_beta[(size_t)n*HH + tid] = 1.f / (1.f + expf(-red[tid][0]));
}

// ---------------- per-chunk delta-rule precompute (tensor-core mma) ---------
// Outputs fp16: qn [t][d], w/u [t][d], knT [d][t], attn [t][t].
#define PSTR 264
#define PSMEM ((2*32*PSTR + 32*33 + 32*36 + 96) * 4)
__global__ __launch_bounds__(256) void precompute_kernel()
{
    extern __shared__ float psm[];
    float*    Kt  = psm;                     // [32][PSTR] k fp32 -> kn tf32
    float*    Qt  = Kt + 32*PSTR;            // [32][PSTR] q fp32 -> qn tf32 -> v tf32
    float*    Am  = Qt + 32*PSTR;            // [32][33]
    unsigned* Ttf = (unsigned*)(Am + 32*33); // [32][36]
    float*    bet = (float*)(Ttf + 32*36);   // [32]
    float*    rnk = bet + 32;                // [32]
    float*    rnq = rnk + 32;                // [32]

    int blk = blockIdx.x;           // (b*HH + h)*NC + c
    int c  = blk % NC;
    int bh = blk / NC;
    int h  = bh % HH;
    int b  = bh / HH;
    int tid = threadIdx.x;
    int l0 = c * 32;
    int wid = tid >> 5, lane = tid & 31;
    int lr = lane >> 2, lk = lane & 3;

    // 1. load k, q tiles (fp16 -> fp32)
    for (int e = tid*4; e < 32*256; e += 1024) {
        int r = e >> 8, d = e & 255;
        size_t gb = ((size_t)(b*LL + l0 + r))*DD + h*DV + d;
        uint2 kh = *(const uint2*)&g_kc_h[gb];
        float2 ka = __half22float2(*(__half2*)&kh.x);
        float2 kb2 = __half22float2(*(__half2*)&kh.y);
        *(float4*)&Kt[r*PSTR + d] = make_float4(ka.x, ka.y, kb2.x, kb2.y);
        uint2 qh = *(const uint2*)&g_qc_h[gb];
        float2 qa = __half22float2(*(__half2*)&qh.x);
        float2 qb2 = __half22float2(*(__half2*)&qh.y);
        *(float4*)&Qt[r*PSTR + d] = make_float4(qa.x, qa.y, qb2.x, qb2.y);
    }
    if (tid < 32) bet[tid] = g_beta[((size_t)(b*LL + l0 + tid))*HH + h];
    __syncthreads();

    // 2. row norms (8 threads per row)
    {
        int r = tid >> 3, part = tid & 7;
        float sk = 0.f, sq = 0.f;
        for (int j = part*32; j < part*32 + 32; j++) {
            float x = Kt[r*PSTR + j]; sk += x*x;
            float y = Qt[r*PSTR + j]; sq += y*y;
        }
        sk += __shfl_down_sync(0xffffffffu, sk, 4, 8);
        sk += __shfl_down_sync(0xffffffffu, sk, 2, 8);
        sk += __shfl_down_sync(0xffffffffu, sk, 1, 8);
        sq += __shfl_down_sync(0xffffffffu, sq, 4, 8);
        sq += __shfl_down_sync(0xffffffffu, sq, 2, 8);
        sq += __shfl_down_sync(0xffffffffu, sq, 1, 8);
        if (part == 0) { rnk[r] = rsqrtf(sk + 1e-6f); rnq[r] = rsqrtf(sq + 1e-6f); }
    }
    __syncthreads();

    // 3. normalize in place (qn fp16 -> global, tf32 -> smem)
    size_t obase = (size_t)blk * (32*256);
    for (int e = tid*4; e < 32*256; e += 1024) {
        int r = e >> 8, d = e & 255;
        float rk = rnk[r], rq = rnq[r];
        float4 kv = *(float4*)&Kt[r*PSTR + d];
        kv.x *= rk; kv.y *= rk; kv.z *= rk; kv.w *= rk;
        unsigned* kd = (unsigned*)&Kt[r*PSTR + d];
        kd[0]=f2tf(kv.x); kd[1]=f2tf(kv.y); kd[2]=f2tf(kv.z); kd[3]=f2tf(kv.w);
        float4 qv = *(float4*)&Qt[r*PSTR + d];
        qv.x *= rq; qv.y *= rq; qv.z *= rq; qv.w *= rq;
        __half2 qh0 = __floats2half2_rn(qv.x, qv.y);
        __half2 qh1 = __floats2half2_rn(qv.z, qv.w);
        uint2 qo = {*(unsigned*)&qh0, *(unsigned*)&qh1};
        *(uint2*)&g_qn_h[obase + e] = qo;
        unsigned* qd = (unsigned*)&Qt[r*PSTR + d];
        qd[0]=f2tf(qv.x); qd[1]=f2tf(qv.y); qd[2]=f2tf(qv.z); qd[3]=f2tf(qv.w);
    }
    __syncthreads();

    // 3b. write kn transposed [dv][time] as fp16 (Kt holds tf32-bit floats)
    for (int e = tid*2; e < 32*256; e += 512) {
        int r = e & 31, d = e >> 5;          // r even
        float v0 = Kt[r*PSTR + d];
        float v1 = Kt[(r+1)*PSTR + d];
        *(__half2*)&g_knT_h[obase + e] = __floats2half2_rn(v0, v1);
    }

    // 4. fused mma: Afull = kn@kn^T, attnF = qn@kn^T  (32x32, K=256)
    {
        int m0 = (wid >> 2) * 16, n0 = (wid & 3) * 8;
        const unsigned* Ku = (const unsigned*)Kt;
        const unsigned* Qu = (const unsigned*)Qt;
        float accA[4] = {0,0,0,0}, accQ[4] = {0,0,0,0};
#pragma unroll 4
        for (int kb = 0; kb < 256; kb += 8) {
            unsigned ak[4], aq[4], bf[2];
            ak[0] = Ku[(m0+lr)*PSTR + kb+lk];
            ak[1] = Ku[(m0+lr+8)*PSTR + kb+lk];
            ak[2] = Ku[(m0+lr)*PSTR + kb+lk+4];
            ak[3] = Ku[(m0+lr+8)*PSTR + kb+lk+4];
            aq[0] = Qu[(m0+lr)*PSTR + kb+lk];
            aq[1] = Qu[(m0+lr+8)*PSTR + kb+lk];
            aq[2] = Qu[(m0+lr)*PSTR + kb+lk+4];
            aq[3] = Qu[(m0+lr+8)*PSTR + kb+lk+4];
            bf[0] = Ku[(n0+lr)*PSTR + kb+lk];
            bf[1] = Ku[(n0+lr)*PSTR + kb+lk+4];
            mma_tf32(accA, ak, bf);
            mma_tf32(accQ, aq, bf);
        }
        size_t abase = (size_t)blk * 1024;
        int r0 = m0 + lr, r1 = r0 + 8, c0 = n0 + 2*lk, c1 = c0 + 1;
        float q00 = (c0 <= r0) ? accQ[0] : 0.f;
        float q01 = (c1 <= r0) ? accQ[1] : 0.f;
        float q10 = (c0 <= r1) ? accQ[2] : 0.f;
        float q11 = (c1 <= r1) ? accQ[3] : 0.f;
        *(__half2*)&g_attn_h[abase + r0*32 + c0] = __floats2half2_rn(q00, q01);
        *(__half2*)&g_attn_h[abase + r1*32 + c0] = __floats2half2_rn(q10, q11);
        Am[r0*33 + c0] = (c0 < r0) ? -bet[r0]*accA[0] : 0.f;
        Am[r0*33 + c1] = (c1 < r0) ? -bet[r0]*accA[1] : 0.f;
        Am[r1*33 + c0] = (c0 < r1) ? -bet[r1]*accA[2] : 0.f;
        Am[r1*33 + c1] = (c1 < r1) ? -bet[r1]*accA[3] : 0.f;
    }
    __syncthreads();

    // 5. iterative inversion (warp 0), then T' = (A+I)*diag(beta) as tf32
    if (tid < 32) {
        int ln = tid;
        for (int i = 1; i < 32; i++) {
            float t = 0.f;
            if (ln < i) for (int p = 0; p < i; p++) t += Am[i*33 + p] * Am[p*33 + ln];
            __syncwarp();
            if (ln < i) Am[i*33 + ln] += t;
            __syncwarp();
        }
    }
    __syncthreads();
    for (int e = tid; e < 1024; e += 256) {
        int i = e >> 5, j = e & 31;
        float t = Am[i*33 + j] + (i == j ? 1.f : 0.f);
        Ttf[i*36 + j] = f2tf(t * bet[j]);
    }
    // 6. load raw v tile (fp16) as tf32 into Qt (reuse)
    __syncthreads();
    for (int e = tid*4; e < 32*256; e += 1024) {
        int r = e >> 8, d = e & 255;
        uint2 vh = *(const uint2*)&g_vc_h[((size_t)(b*LL + l0 + r))*DD + h*DV + d];
        float2 va = __half22float2(*(__half2*)&vh.x);
        float2 vb2 = __half22float2(*(__half2*)&vh.y);
        unsigned* qd = (unsigned*)&Qt[r*PSTR + d];
        qd[0]=f2tf(va.x); qd[1]=f2tf(va.y); qd[2]=f2tf(vb2.x); qd[3]=f2tf(vb2.y);
    }
    __syncthreads();

    // 7. u = T'@v, w = T'@kn   (32x256, K=32) — fp16 outputs
    {
        int m0 = (wid & 1) * 16;
        int nb = (wid >> 1) * 64;
        const unsigned* Ku = (const unsigned*)Kt;
        const unsigned* Vu = (const unsigned*)Qt;
        unsigned a[4][4];
#pragma unroll
        for (int kk = 0; kk < 4; kk++) {
            int kb = kk*8;
            a[kk][0] = Ttf[(m0+lr)*36 + kb+lk];
            a[kk][1] = Ttf[(m0+lr+8)*36 + kb+lk];
            a[kk][2] = Ttf[(m0+lr)*36 + kb+lk+4];
            a[kk][3] = Ttf[(m0+lr+8)*36 + kb+lk+4];
        }
#pragma unroll
        for (int nt = 0; nt < 8; nt++) {
            int n0 = nb + nt*8;
            float au[4] = {0,0,0,0}, aw[4] = {0,0,0,0};
#pragma unroll
            for (int kk = 0; kk < 4; kk++) {
                int kb = kk*8;
                unsigned bu[2], bw[2];
                bu[0] = Vu[(kb+lk)*PSTR + n0+lr];
                bu[1] = Vu[(kb+lk+4)*PSTR + n0+lr];
                bw[0] = Ku[(kb+lk)*PSTR + n0+lr];
                bw[1] = Ku[(kb+lk+4)*PSTR + n0+lr];
                mma_tf32(au, a[kk], bu);
                mma_tf32(aw, a[kk], bw);
            }
            int r0 = m0 + lr, r1 = r0 + 8, cc = n0 + 2*lk;
            *(__half2*)&g_u_h[obase + r0*256 + cc] = __floats2half2_rn(au[0], au[1]);
            *(__half2*)&g_u_h[obase + r1*256 + cc] = __floats2half2_rn(au[2], au[3]);
            *(__half2*)&g_w_h[obase + r0*256 + cc] = __floats2half2_rn(aw[0], aw[1]);
            *(__half2*)&g_w_h[obase + r1*256 + cc] = __floats2half2_rn(aw[2], aw[3]);
        }
    }
}

// --------------- sequential inter-chunk scan (fp16 tensor-core mma) ---------
#define SFW 40
#define SCAN_SMEM 88576
__global__ __launch_bounds__(256) void scan_kernel()
{
    extern __shared__ char ssm[];
    float*    Sf  = (float*)ssm;                      // [256][40] f32
    unsigned* Sh  = (unsigned*)(ssm + 40960);         // [32][132] words
    unsigned* Tw  = (unsigned*)(ssm + 57856);         // tile (max 20480B)
    float*    Ui  = (float*)(ssm + 78336);            // [32][40] f32
    unsigned* Uh  = (unsigned*)(ssm + 83456);         // [32][20] words
    unsigned* Ah  = (unsigned*)(ssm + 86016);         // [32][20] words
    __half*   ShH = (__half*)Sh;
    __half*   UhH = (__half*)Uh;
    __half*   TwH = (__half*)Tw;

    int blk = blockIdx.x;
    int g  = blk & (NG-1);
    int bh = blk >> 3;
    int b  = bh >> 2;
    int h  = bh & 3;
    int tid = threadIdx.x;
    int wid = tid >> 5, lane = tid & 31;
    int lr = lane >> 2, lk = lane & 3;
    int m0 = (wid >> 2) * 16;
    int n0 = (wid & 3) * 8;

    for (int e = tid; e < 256*SFW; e += 256) Sf[e] = 0.f;
    for (int e = tid; e < 32*132; e += 256) Sh[e] = 0u;
    __syncthreads();

    for (int c = 0; c < NC; c++) {
        size_t base = ((size_t)bh*NC + c) * (32*256);
        size_t abase = ((size_t)bh*NC + c) * 1024;

        for (int e = tid*2; e < 1024; e += 512) {
            int r = e >> 5, j = e & 31;
            unsigned uw = *(const unsigned*)&g_u_h[base + r*256 + g*32 + j];
            float2 uf = __half22float2(*(__half2*)&uw);
            Ui[r*SFW + j] = uf.x; Ui[r*SFW + j + 1] = uf.y;
        }
        {
            int e = tid*4;
            int r = e >> 5, j = e & 31;
            *(uint2*)&Ah[r*20 + (j >> 1)] = *(const uint2*)&g_attn_h[abase + e];
        }
        for (int e = tid*8; e < 8192; e += 2048) {
            int r = e >> 8, jj = e & 255;
            *(uint4*)&TwH[r*264 + jj] = *(const uint4*)&g_w_h[base + e];
        }
        __syncthreads();

        // (1) u_i = u - w@S    (32x32, K=256, fp16)
        {
            float acc[4] = {0.f, 0.f, 0.f, 0.f};
#pragma unroll 4
            for (int kb = 0; kb < 256; kb += 16) {
                int kw = (kb >> 1) + lk;
                unsigned a[4], bf[2];
                a[0] = Tw[(m0+lr)*132 + kw];
                a[1] = Tw[(m0+lr+8)*132 + kw];
                a[2] = Tw[(m0+lr)*132 + kw + 4];
                a[3] = Tw[(m0+lr+8)*132 + kw + 4];
                bf[0] = Sh[(n0+lr)*132 + kw];
                bf[1] = Sh[(n0+lr)*132 + kw + 4];
                mma_f16(acc, a, bf);
            }
            int r0 = m0 + lr, r1 = r0 + 8, cb = n0 + 2*lk;
            float u0 = Ui[r0*SFW+cb]   - acc[0];
            float u1 = Ui[r0*SFW+cb+1] - acc[1];
            float u2 = Ui[r1*SFW+cb]   - acc[2];
            float u3 = Ui[r1*SFW+cb+1] - acc[3];
            UhH[cb*40 + r0]     = __float2half_rn(u0);
            UhH[(cb+1)*40 + r0] = __float2half_rn(u1);
            UhH[cb*40 + r1]     = __float2half_rn(u2);
            UhH[(cb+1)*40 + r1] = __float2half_rn(u3);
        }
        __syncthreads();

        for (int e = tid*8; e < 8192; e += 2048) {
            int r = e >> 8, jj = e & 255;
            *(uint4*)&TwH[r*264 + jj] = *(const uint4*)&g_qn_h[base + e];
        }
        __syncthreads();

        // (2) o = q@S + attn@u_i  -> g_delta (fp16)
        {
            float acc[4] = {0.f, 0.f, 0.f, 0.f};
#pragma unroll 4
            for (int kb = 0; kb < 256; kb += 16) {
                int kw = (kb >> 1) + lk;
                unsigned a[4], bf[2];
                a[0] = Tw[(m0+lr)*132 + kw];
                a[1] = Tw[(m0+lr+8)*132 + kw];
                a[2] = Tw[(m0+lr)*132 + kw + 4];
                a[3] = Tw[(m0+lr+8)*132 + kw + 4];
                bf[0] = Sh[(n0+lr)*132 + kw];
                bf[1] = Sh[(n0+lr)*132 + kw + 4];
                mma_f16(acc, a, bf);
            }
#pragma unroll
            for (int kb = 0; kb < 32; kb += 16) {
                int kw = (kb >> 1) + lk;
                unsigned a[4], bf[2];
                a[0] = Ah[(m0+lr)*20 + kw];
                a[1] = Ah[(m0+lr+8)*20 + kw];
                a[2] = Ah[(m0+lr)*20 + kw + 4];
                a[3] = Ah[(m0+lr+8)*20 + kw + 4];
                bf[0] = Uh[(n0+lr)*20 + kw];
                bf[1] = Uh[(n0+lr)*20 + kw + 4];
                mma_f16(acc, a, bf);
            }
            size_t ob = ((size_t)(b*LL + c*32 + m0 + lr))*DD + h*DV + g*32 + n0 + 2*lk;
            *(__half2*)&g_delta_h[ob]        = __floats2half2_rn(acc[0], acc[1]);
            *(__half2*)&g_delta_h[ob + 8*DD] = __floats2half2_rn(acc[2], acc[3]);
        }
        __syncthreads();

        for (int e = tid*8; e < 8192; e += 2048) {
            int r = e >> 5, jj = e & 31;
            *(uint4*)&TwH[r*40 + jj] = *(const uint4*)&g_knT_h[base + e];
        }
        __syncthreads();

        // (3) S += k^T @ u_i
#pragma unroll
        for (int t = 0; t < 2; t++) {
            int tm = (wid*2 + t) * 16;
#pragma unroll
            for (int tn = 0; tn < 4; tn++) {
                int nn = tn*8;
                int r0 = tm + lr, r1 = r0 + 8, cb = nn + 2*lk;
                float acc[4];
                acc[0] = Sf[r0*SFW+cb]; acc[1] = Sf[r0*SFW+cb+1];
                acc[2] = Sf[r1*SFW+cb]; acc[3] = Sf[r1*SFW+cb+1];
#pragma unroll
                for (int kb = 0; kb < 32; kb += 16) {
                    int kw = (kb >> 1) + lk;
                    unsigned a[4], bf[2];
                    a[0] = Tw[(tm+lr)*20 + kw];
                    a[1] = Tw[(tm+lr+8)*20 + kw];
                    a[2] = Tw[(tm+lr)*20 + kw + 4];
                    a[3] = Tw[(tm+lr+8)*20 + kw + 4];
                    bf[0] = Uh[(nn+lr)*20 + kw];
                    bf[1] = Uh[(nn+lr)*20 + kw + 4];
                    mma_f16(acc, a, bf);
                }
                Sf[r0*SFW+cb] = acc[0]; Sf[r0*SFW+cb+1] = acc[1];
                Sf[r1*SFW+cb] = acc[2]; Sf[r1*SFW+cb+1] = acc[3];
                ShH[cb*264 + r0]     = __float2half_rn(acc[0]);
                ShH[(cb+1)*264 + r0] = __float2half_rn(acc[1]);
                ShH[cb*264 + r1]     = __float2half_rn(acc[2]);
                ShH[(cb+1)*264 + r1] = __float2half_rn(acc[3]);
            }
        }
        __syncthreads();
    }
}

// ------------------- per-(head,channel) FIR conv (fp16 io) ------------------
template<int K>
__global__ __launch_bounds__(256) void fir_kernel(
    const float* __restrict__ fw, __half* __restrict__ y)
{
    __shared__ float2 vbuf[(128 + K - 1) * 16];
    __shared__ float2 wbuf[16 * K];
    int bh = blockIdx.x;
    int b = bh / HH, h = bh % HH;
    int l0 = blockIdx.y * 128;
    int d0 = blockIdx.z * 32;
    int tid = threadIdx.x;

    for (int idx = tid; idx < 16*K; idx += 256) {
        int dp = idx / K, t = idx % K;
        float2 wv;
        wv.x = fw[(size_t)(h*DV + d0 + 2*dp)*K + t];
        wv.y = fw[(size_t)(h*DV + d0 + 2*dp + 1)*K + t];
        wbuf[dp*K + t] = wv;
    }
    for (int idx = tid; idx < (128 + K - 1)*16; idx += 256) {
        int lrr = idx >> 4, dp = idx & 15;
        int l = l0 - (K - 1) + lrr;
        vbuf[idx] = (l >= 0)
            ? __half22float2(*(const __half2*)&g_vc_h[((size_t)(b*LL + l))*DD + h*DV + d0 + 2*dp])
            : make_float2(0.f, 0.f);
    }
    __syncthreads();

    int dp = tid & 15;
    int lr0 = (tid >> 4) * 8;
    for (int m = 0; m < 8; m++) {
        int lrr = lr0 + m;
        float2 acc = {0.f, 0.f};
#pragma unroll
        for (int t = 0; t < K; t++) {
            float2 v = vbuf[(lrr + t)*16 + dp];
            float2 wv = wbuf[dp*K + t];
            acc.x = fmaf(v.x, wv.x, acc.x);
            acc.y = fmaf(v.y, wv.y, acc.y);
        }
        *(__half2*)&y[((size_t)(b*LL + l0 + lrr))*DD + h*DV + d0 + 2*dp]
            = __floats2half2_rn(acc.x, acc.y);
    }
}

// ------------- gate input assembly (hs + stats), stored as fp16 -------------
__global__ __launch_bounds__(256) void stats_kernel(const float* __restrict__ hs)
{
    int n = blockIdx.x, tid = threadIdx.x;
    {
        int i = tid * 4;
        float4 v = *(const float4*)&hs[(size_t)n*DD + i];
        __half2 lo = __floats2half2_rn(v.x, v.y);
        __half2 hi = __floats2half2_rn(v.z, v.w);
        uint2 o = {*(unsigned*)&lo, *(unsigned*)&hi};
        *(uint2*)&g_gatein_h[(size_t)n*GINP + i] = o;
    }
    if (tid < 32) g_gatein_h[(size_t)n*GINP + GIN + tid] = __float2half_rn(0.f);
    int warp = tid >> 5, lane = tid & 31;
    for (int rep = 0; rep < 2; rep++) {
        int combo = warp*2 + rep;
        int path = combo >> 2, h = combo & 3;
        const __half* p;
        if      (path == 0) p = g_short_h;
        else if (path == 1) p = g_long_h;
        else if (path == 2) p = g_delta_h;
        else                p = g_vc_h;
        p += (size_t)n*DD + h*DV;
        float s1 = 0.f, s2 = 0.f;
        for (int j = lane; j < 256; j += 32) {
            float x = __half2float(p[j]); s1 += x; s2 += x*x;
        }
#pragma unroll
        for (int st = 16; st > 0; st >>= 1) {
            s1 += __shfl_down_sync(0xffffffffu, s1, st);
            s2 += __shfl_down_sync(0xffffffffu, s2, st);
        }
        if (lane == 0) {
            float m  = s1 * (1.f/256.f);
            float va = s2 * (1.f/256.f) - m*m;
            g_gatein_h[(size_t)n*GINP + DD + path*8 + h*2]     = __float2half_rn(m);
            g_gatein_h[(size_t)n*GINP + DD + path*8 + h*2 + 1] = __float2half_rn(va);
        }
    }
}

// ------------------- gate2 + softmax + floor (fp16 hmid) --------------------
__global__ __launch_bounds__(256) void gate2_kernel(
    const float* __restrict__ w2, const float* __restrict__ log_temp,
    const float* __restrict__ base_bias, const float* __restrict__ floor_raw)
{
    __shared__ float hrow[HID];
    __shared__ float lg[16];
    int n = blockIdx.x, tid = threadIdx.x;
    for (int i = tid*2; i < HID; i += 512) {
        float2 v = __half22float2(*(const __half2*)&g_hmid_h[(size_t)n*HID + i]);
        hrow[i] = v.x; hrow[i+1] = v.y;
    }
    __syncthreads();
    int warp = tid >> 5, lane = tid & 31;
    for (int rep = 0; rep < 2; rep++) {
        int o = warp*2 + rep;
        const float* wr = w2 + (size_t)o*HID;
        float s = 0.f;
        for (int i = lane; i < HID; i += 32) s = fmaf(hrow[i], wr[i], s);
#pragma unroll
        for (int st = 16; st > 0; st >>= 1) s += __shfl_down_sync(0xffffffffu, s, st);
        if (lane == 0) lg[o] = s;
    }
    __syncthreads();
    if (tid < 4) {
        int h = tid;
        float temp = log1pf(expf(log_temp[h])) + 1e-4f;
        float z[4], m = -1e30f;
#pragma unroll
        for (int i = 0; i < 4; i++) {
            z[i] = (lg[h*4+i] + base_bias[h*4+i]) / temp;
            m = fmaxf(m, z[i]);
        }
        float e[4], s = 0.f;
#pragma unroll
        for (int i = 0; i < 4; i++) { e[i] = expf(z[i] - m); s += e[i]; }
        float p[4], s2 = 0.f;
#pragma unroll
        for (int i = 0; i < 4; i++) {
            p[i] = e[i] / s;
            float f = 0.05f / (1.f + expf(-floor_raw[h*4+i]));
            p[i] = fmaxf(p[i], f);
            s2 += p[i];
        }
#pragma unroll
        for (int i = 0; i < 4; i++) g_probs[(size_t)n*16 + h*4 + i] = p[i] / s2;
    }
}

// ------------- path mix + RMS norm, output stored as fp16 -------------------
__global__ __launch_bounds__(256) void mix_kernel(const float* __restrict__ onorm)
{
    __shared__ float pr[16];
    __shared__ float wsum[8];
    int n = blockIdx.x, tid = threadIdx.x;
    if (tid < 16) pr[tid] = g_probs[(size_t)n*16 + tid];
    __syncthreads();
    int h = tid >> 6;
    int dd = (tid & 63) * 4;
    size_t pb = (size_t)n*DD + h*DV + dd;
    uint2 sraw = *(const uint2*)&g_short_h[pb];
    uint2 lraw = *(const uint2*)&g_long_h[pb];
    uint2 draw = *(const uint2*)&g_delta_h[pb];
    uint2 vraw = *(const uint2*)&g_vc_h[pb];
    float2 sa = __half22float2(*(__half2*)&sraw.x), sb = __half22float2(*(__half2*)&sraw.y);
    float2 la = __half22float2(*(__half2*)&lraw.x), lb = __half22float2(*(__half2*)&lraw.y);
    float2 da = __half22float2(*(__half2*)&draw.x), db = __half22float2(*(__half2*)&draw.y);
    float2 va = __half22float2(*(__half2*)&vraw.x), vb = __half22float2(*(__half2*)&vraw.y);
    float p0 = pr[h*4+0], p1 = pr[h*4+1], p2 = pr[h*4+2], p3 = pr[h*4+3];
    float o[4];
    o[0] = p0*sa.x + p1*la.x + p2*da.x + p3*va.x;
    o[1] = p0*sa.y + p1*la.y + p2*da.y + p3*va.y;
    o[2] = p0*sb.x + p1*lb.x + p2*db.x + p3*vb.x;
    o[3] = p0*sb.y + p1*lb.y + p2*db.y + p3*vb.y;
    float ss = o[0]*o[0] + o[1]*o[1] + o[2]*o[2] + o[3]*o[3];
#pragma unroll
    for (int st = 16; st > 0; st >>= 1) ss += __shfl_down_sync(0xffffffffu, ss, st);
    int warp = tid >> 5, lane = tid & 31;
    if (lane == 0) wsum[warp] = ss;
    __syncthreads();
    float tot = wsum[h*2] + wsum[h*2+1];
    float scale = rsqrtf(tot * (1.f/256.f) + 1e-5f);
    __half2 h0 = __floats2half2_rn(o[0]*scale*onorm[dd],   o[1]*scale*onorm[dd+1]);
    __half2 h1 = __floats2half2_rn(o[2]*scale*onorm[dd+2], o[3]*scale*onorm[dd+3]);
    uint2 pk = {*(unsigned*)&h0, *(unsigned*)&h1};
    *(uint2*)&g_mix_h[pb] = pk;
}

// ------------------------- launch ------------------------------------------
extern "C" void kernel_launch(void* const* d_in, const int* in_sizes, int n_in,
                              void* d_out, int out_size)
{
    const float* hs        = (const float*)d_in[0];
    const float* Wq        = (const float*)d_in[1];
    const float* Wk        = (const float*)d_in[2];
    const float* Wv        = (const float*)d_in[3];
    const float* Wb        = (const float*)d_in[4];
    const float* qconv_w   = (const float*)d_in[5];
    const float* kconv_w   = (const float*)d_in[6];
    const float* vconv_w   = (const float*)d_in[7];
    const float* fir_s     = (const float*)d_in[8];
    const float* fir_l     = (const float*)d_in[9];
    const float* gate_w1   = (const float*)d_in[10];
    const float* gate_b1   = (const float*)d_in[11];
    const float* gate_w2   = (const float*)d_in[12];
    const float* log_temp  = (const float*)d_in[13];
    const float* base_bias = (const float*)d_in[14];
    const float* floor_raw = (const float*)d_in[15];
    const float* onorm_w   = (const float*)d_in[16];
    const float* Wo        = (const float*)d_in[17];
    float* out = (float*)d_out;

    void *p_qlin, *p_klin, *p_vlin, *p_qc, *p_kc, *p_vc, *p_hmid, *p_short, *p_long;
    void *p_hsh, *p_wqh, *p_wkh, *p_wvh, *p_woh, *p_gw1h, *p_gateinh, *p_mixh;
    cudaGetSymbolAddress(&p_qlin, g_qlin_h);
    cudaGetSymbolAddress(&p_klin, g_klin_h);
    cudaGetSymbolAddress(&p_vlin, g_vlin_h);
    cudaGetSymbolAddress(&p_qc, g_qc_h);
    cudaGetSymbolAddress(&p_kc, g_kc_h);
    cudaGetSymbolAddress(&p_vc, g_vc_h);
    cudaGetSymbolAddress(&p_hmid, g_hmid_h);
    cudaGetSymbolAddress(&p_short, g_short_h);
    cudaGetSymbolAddress(&p_long, g_long_h);
    cudaGetSymbolAddress(&p_hsh, g_hs_h);
    cudaGetSymbolAddress(&p_wqh, g_wq_h);
    cudaGetSymbolAddress(&p_wkh, g_wk_h);
    cudaGetSymbolAddress(&p_wvh, g_wv_h);
    cudaGetSymbolAddress(&p_woh, g_wo_h);
    cudaGetSymbolAddress(&p_gw1h, g_gw1_h);
    cudaGetSymbolAddress(&p_gateinh, g_gatein_h);
    cudaGetSymbolAddress(&p_mixh, g_mix_h);

    cudaFuncSetAttribute(scan_kernel,
        cudaFuncAttributeMaxDynamicSharedMemorySize, SCAN_SMEM);
    cudaFuncSetAttribute(precompute_kernel,
        cudaFuncAttributeMaxDynamicSharedMemorySize, PSMEM);
    cudaFuncSetAttribute(hgemm,
        cudaFuncAttributeMaxDynamicSharedMemorySize, HGEMM_SMEM);

    dim3 blk(256);

    // 0. pre-convert hs + weights to fp16 (gate_w1 padded separately)
    cvt_h6<<<dim3(NROW*DD/1024, 6), blk>>>(
        hs, (__half*)p_hsh, NROW*DD,
        Wq, (__half*)p_wqh, DD*DD,
        Wk, (__half*)p_wkh, DD*DD,
        Wv, (__half*)p_wvh, DD*DD,
        Wo, (__half*)p_woh, DD*DD,
        nullptr, nullptr, 0);
    cvt_gw1pad<<<(HID*GINP/4 + 255)/256, blk>>>(gate_w1);

    // q/k/v projections — fp16 outputs (mode 2)
    hgemm<<<dim3(DD/128, NROW/128, 3), blk, HGEMM_SMEM>>>(
        (const __half*)p_hsh,
        (const __half*)p_wqh, (const __half*)p_wkh, (const __half*)p_wvh,
        (float*)p_qlin, (float*)p_klin, (float*)p_vlin,
        nullptr, NROW, DD, DD, 2);

    // causal conv4 + SiLU (fp16 io, 4 elems/thread)
    conv4_silu3<<<dim3(NROW*DD/1024, 3), blk>>>(
        (const __half*)p_qlin, (const __half*)p_klin, (const __half*)p_vlin,
        qconv_w, kconv_w, vconv_w,
        (__half*)p_qc, (__half*)p_kc, (__half*)p_vc);

    // beta (reads fp16 hs)
    beta_kernel<<<NROW, 128>>>(Wb);

    // delta-rule
    precompute_kernel<<<BB*HH*NC, blk, PSMEM>>>();
    scan_kernel<<<BB*HH*NG, blk, SCAN_SMEM>>>();

    // FIR paths
    fir_kernel<3><<<dim3(BB*HH, LL/128, DV/32), blk>>>(fir_s, (__half*)p_short);
    fir_kernel<63><<<dim3(BB*HH, LL/128, DV/32), blk>>>(fir_l, (__half*)p_long);

    // gate (hmid fp16: mode 1|2 = GELU + fp16 out)
    stats_kernel<<<NROW, blk>>>(hs);
    hgemm<<<dim3(HID/128, NROW/128, 1), blk, HGEMM_SMEM>>>(
        (const __half*)p_gateinh,
        (const __half*)p_gw1h, nullptr, nullptr,
        (float*)p_hmid, nullptr, nullptr,
        gate_b1, NROW, HID, GINP, 3);
    gate2_kernel<<<NROW, blk>>>(gate_w2, log_temp, base_bias, floor_raw);

    // mix + RMS norm
    mix_kernel<<<NROW, blk>>>(onorm_w);

    // output projection (fp32 out)
    hgemm<<<dim3(DD/128, NROW/128, 1), blk, HGEMM_SMEM>>>(
        (const __half*)p_mixh,
        (const __half*)p_woh, nullptr, nullptr,
        out, nullptr, nullptr,
        nullptr, NROW, DD, DD, 0);
}

// round 16
// speedup vs baseline: 1.3947x; 1.3588x over previous
#include <cuda_runtime.h>
#include <cuda_fp16.h>
#include <math.h>
#include <stdint.h>

#define BB 2
#define LL 2048
#define DD 1024
#define HH 4
#define DV 256
#define CKN 32
#define NC 64              // LL / CKN
#define NROW (BB*LL)       // 4096
#define GIN 1056
#define GINP 1088          // padded to multiple of 64
#define HID 2048
#define NG 8               // Dv groups of 32 in the scan

// ------------------------- scratch (device globals) -------------------------
__device__ float g_beta[NROW*HH];
__device__ float g_probs[NROW*16];
// fp16 intermediates + GEMM operands
__device__ __half g_qn_h[NROW*DD];       // [bh][c][time32][dv256]
__device__ __half g_knT_h[NROW*DD];      // [bh][c][dv256][time32]
__device__ __half g_u_h[NROW*DD];        // [bh][c][time32][dv256]
__device__ __half g_w_h[NROW*DD];        // [bh][c][time32][dv256]
__device__ __half g_attn_h[BB*HH*NC*CKN*CKN];
__device__ __half g_delta_h[NROW*DD];
__device__ __half g_short_h[NROW*DD];
__device__ __half g_long_h[NROW*DD];
__device__ __half g_hmid_h[NROW*HID];
__device__ __half g_qlin_h[NROW*DD];
__device__ __half g_klin_h[NROW*DD];
__device__ __half g_vlin_h[NROW*DD];
__device__ __half g_qc_h[NROW*DD];
__device__ __half g_kc_h[NROW*DD];
__device__ __half g_vc_h[NROW*DD];
__device__ __half g_hs_h[NROW*DD];
__device__ __half g_wq_h[DD*DD];
__device__ __half g_wk_h[DD*DD];
__device__ __half g_wv_h[DD*DD];
__device__ __half g_wo_h[DD*DD];
__device__ __half g_gw1_h[HID*GINP];
__device__ __half g_gatein_h[NROW*GINP];
__device__ __half g_mix_h[NROW*DD];

// ------------------------- helpers ------------------------------------------
__device__ __forceinline__ unsigned f2tf(float x) {
    unsigned r;
    asm("cvt.rna.tf32.f32 %0, %1;" : "=r"(r) : "f"(x));
    return r;
}

__device__ __forceinline__ void mma_tf32(float* c, const unsigned* a, const unsigned* b) {
    asm volatile(
        "mma.sync.aligned.m16n8k8.row.col.f32.tf32.tf32.f32 "
        "{%0,%1,%2,%3}, {%4,%5,%6,%7}, {%8,%9}, {%0,%1,%2,%3};"
        : "+f"(c[0]), "+f"(c[1]), "+f"(c[2]), "+f"(c[3])
        : "r"(a[0]), "r"(a[1]), "r"(a[2]), "r"(a[3]), "r"(b[0]), "r"(b[1]));
}

__device__ __forceinline__ void mma_f16(float* c, const unsigned* a, const unsigned* b) {
    asm volatile(
        "mma.sync.aligned.m16n8k16.row.col.f32.f16.f16.f32 "
        "{%0,%1,%2,%3}, {%4,%5,%6,%7}, {%8,%9}, {%0,%1,%2,%3};"
        : "+f"(c[0]), "+f"(c[1]), "+f"(c[2]), "+f"(c[3])
        : "r"(a[0]), "r"(a[1]), "r"(a[2]), "r"(a[3]), "r"(b[0]), "r"(b[1]));
}

#define LDSM4(r, addr)                                                        \
    asm volatile("ldmatrix.sync.aligned.m8n8.x4.shared.b16 {%0,%1,%2,%3}, [%4];" \
        : "=r"((r)[0]), "=r"((r)[1]), "=r"((r)[2]), "=r"((r)[3]) : "r"(addr))

// ------------------------- bulk fp32 -> fp16 conversion ---------------------
__global__ __launch_bounds__(256) void cvt_h6(
    const float* __restrict__ s0, __half* __restrict__ d0, int n0,
    const float* __restrict__ s1, __half* __restrict__ d1, int n1,
    const float* __restrict__ s2, __half* __restrict__ d2, int n2,
    const float* __restrict__ s3, __half* __restrict__ d3, int n3,
    const float* __restrict__ s4, __half* __restrict__ d4, int n4,
    const float* __restrict__ s5, __half* __restrict__ d5, int n5)
{
    const float* s; __half* d; int n;
    switch (blockIdx.y) {
        case 0: s=s0; d=d0; n=n0; break;
        case 1: s=s1; d=d1; n=n1; break;
        case 2: s=s2; d=d2; n=n2; break;
        case 3: s=s3; d=d3; n=n3; break;
        case 4: s=s4; d=d4; n=n4; break;
        default: s=s5; d=d5; n=n5; break;
    }
    int i = (blockIdx.x * 256 + threadIdx.x) * 4;
    if (i < n) {
        float4 v = *(const float4*)(s + i);
        __half2 lo = __floats2half2_rn(v.x, v.y);
        __half2 hi = __floats2half2_rn(v.z, v.w);
        uint2 o = {*(unsigned*)&lo, *(unsigned*)&hi};
        *(uint2*)(d + i) = o;
    }
}

// --------- gate_w1 fp32[HID][GIN] -> fp16[HID][GINP] with zero pad ----------
__global__ __launch_bounds__(256) void cvt_gw1pad(const float* __restrict__ src)
{
    int i = (blockIdx.x * 256 + threadIdx.x) * 4;
    if (i >= HID*GINP) return;
    int row = i / GINP, col = i % GINP;
    float4 v;
    if (col < GIN) v = *(const float4*)&src[(size_t)row*GIN + col];
    else v = make_float4(0.f, 0.f, 0.f, 0.f);
    __half2 lo = __floats2half2_rn(v.x, v.y);
    __half2 hi = __floats2half2_rn(v.z, v.w);
    uint2 o = {*(unsigned*)&lo, *(unsigned*)&hi};
    *(uint2*)&g_gw1_h[i] = o;
}

// ---------------- fp16 tensor GEMM: C = A(MxK) @ B(NxK)^T -------------------
// K=64 per stage, 2-stage cp.async pipeline, 128x128 tile, ldmatrix frags.
// mode bit0: +bias, exact GELU.  mode bit1: fp16 out.
#define HSTRB 144
#define HSTAGE_BYTES (128*HSTRB)        // 18432
#define HGEMM_SMEM (4*HSTAGE_BYTES)     // 73728

#define HLOAD64(kt, st) do {                                                   \
    const __half* Ap_ = A + (size_t)bm*K + (kt)*64;                            \
    const __half* Bp_ = B + (size_t)bn*K + (kt)*64;                            \
    _Pragma("unroll")                                                          \
    for (int i_ = 0; i_ < 4; i_++) {                                           \
        int e_ = tid + i_*256;                                                 \
        int row_ = e_ >> 3, seg_ = e_ & 7;                                     \
        unsigned doff_ = (unsigned)row_*HSTRB + (unsigned)seg_*16;             \
        asm volatile("cp.async.cg.shared.global [%0], [%1], 16;"               \
            :: "r"(smb + (unsigned)((st)*HSTAGE_BYTES) + doff_),               \
               "l"(Ap_ + (size_t)row_*K + seg_*8));                            \
        asm volatile("cp.async.cg.shared.global [%0], [%1], 16;"               \
            :: "r"(smb + (unsigned)(2*HSTAGE_BYTES + (st)*HSTAGE_BYTES) + doff_), \
               "l"(Bp_ + (size_t)row_*K + seg_*8));                            \
    }                                                                          \
} while (0)

__global__ __launch_bounds__(256, 2) void hgemm(
    const __half* __restrict__ A,
    const __half* __restrict__ Bm0, const __half* __restrict__ Bm1, const __half* __restrict__ Bm2,
    float* __restrict__ Cm0, float* __restrict__ Cm1, float* __restrict__ Cm2,
    const float* __restrict__ bias, int M, int N, int K, int mode)
{
    extern __shared__ char tsm[];

    const __half* B = (blockIdx.z == 0) ? Bm0 : (blockIdx.z == 1) ? Bm1 : Bm2;
    float*        C = (blockIdx.z == 0) ? Cm0 : (blockIdx.z == 1) ? Cm1 : Cm2;

    int tid = threadIdx.x;
    int bm = blockIdx.y * 128, bn = blockIdx.x * 128;
    unsigned smb;
    asm("{ .reg .u64 t; cvta.to.shared.u64 t, %1; cvt.u32.u64 %0, t; }"
        : "=r"(smb) : "l"(tsm));

    int wid = tid >> 5, lane = tid & 31;
    int wm = (wid >> 2) * 64, wn = (wid & 3) * 32;
    int lr = lane >> 2, lk = lane & 3;

    int a_row = (lane & 7) + ((lane >> 3) & 1) * 8;
    int a_kb  = (lane >> 4) * 16;
    int b_row = (lane & 7) + ((lane >> 4) & 1) * 8;
    int b_kb  = ((lane >> 3) & 1) * 16;

    float acc[4][4][4];
#pragma unroll
    for (int mi = 0; mi < 4; mi++)
#pragma unroll
        for (int ni = 0; ni < 4; ni++)
#pragma unroll
            for (int j = 0; j < 4; j++) acc[mi][ni][j] = 0.f;

    int niter = K >> 6;

    HLOAD64(0, 0);
    asm volatile("cp.async.commit_group;");

    for (int t = 0; t < niter; t++) {
        asm volatile("cp.async.wait_group 0;");
        __syncthreads();
        if (t + 1 < niter) {
            HLOAD64(t + 1, (t + 1) & 1);
            asm volatile("cp.async.commit_group;");
        }
        int cur = t & 1;
        unsigned a_base = smb + (unsigned)(cur*HSTAGE_BYTES);
        unsigned b_base = smb + (unsigned)(2*HSTAGE_BYTES + cur*HSTAGE_BYTES);
#pragma unroll
        for (int ks = 0; ks < 4; ks++) {
            unsigned af[4][4], bq[2][4];
#pragma unroll
            for (int mi = 0; mi < 4; mi++) {
                unsigned addr = a_base + (unsigned)((wm + mi*16 + a_row)*HSTRB + ks*32 + a_kb);
                LDSM4(af[mi], addr);
            }
#pragma unroll
            for (int nq = 0; nq < 2; nq++) {
                unsigned addr = b_base + (unsigned)((wn + nq*16 + b_row)*HSTRB + ks*32 + b_kb);
                LDSM4(bq[nq], addr);
            }
#pragma unroll
            for (int mi = 0; mi < 4; mi++)
#pragma unroll
                for (int ni = 0; ni < 4; ni++)
                    mma_f16(acc[mi][ni], af[mi], &bq[ni >> 1][(ni & 1) * 2]);
        }
        __syncthreads();
    }

#pragma unroll
    for (int mi = 0; mi < 4; mi++) {
        int r0 = bm + wm + mi*16 + lr;
#pragma unroll
        for (int ni = 0; ni < 4; ni++) {
            int c = bn + wn + ni*8 + 2*lk;
            float v[4] = {acc[mi][ni][0], acc[mi][ni][1], acc[mi][ni][2], acc[mi][ni][3]};
            if (mode & 1) {
                float b0 = bias[c], b1 = bias[c+1];
                v[0] += b0; v[1] += b1; v[2] += b0; v[3] += b1;
#pragma unroll
                for (int j = 0; j < 4; j++)
                    v[j] = 0.5f * v[j] * (1.f + erff(v[j] * 0.70710678118654752f));
            }
            if (mode & 2) {
                __half* Ch = (__half*)C;
                *(__half2*)&Ch[(size_t)r0*N + c]     = __floats2half2_rn(v[0], v[1]);
                *(__half2*)&Ch[(size_t)(r0+8)*N + c] = __floats2half2_rn(v[2], v[3]);
            } else {
                float2 lo = {v[0], v[1]};
                float2 hi = {v[2], v[3]};
                *(float2*)&C[(size_t)r0*N + c]       = lo;
                *(float2*)&C[(size_t)(r0+8)*N + c]   = hi;
            }
        }
    }
}

// ------------- depthwise causal conv4 + SiLU, fp16 io, 4 elems/thread -------
__global__ __launch_bounds__(256) void conv4_silu3(
    const __half* __restrict__ x0, const __half* __restrict__ x1, const __half* __restrict__ x2,
    const float* __restrict__ w0, const float* __restrict__ w1, const float* __restrict__ w2,
    __half* __restrict__ y0, __half* __restrict__ y1, __half* __restrict__ y2)
{
    const __half* x; const float* w; __half* y;
    if (blockIdx.y == 0)      { x = x0; w = w0; y = y0; }
    else if (blockIdx.y == 1) { x = x1; w = w1; y = y1; }
    else                      { x = x2; w = w2; y = y2; }
    int q = blockIdx.x * 256 + threadIdx.x;     // quad index over NROW*DD/4
    int dq = q & (DD/4 - 1);
    int l = (q >> 8) & (LL - 1);
    int d = dq * 4;
    float4 w0v = *(const float4*)(w + d*4);
    float4 w1v = *(const float4*)(w + d*4 + 4);
    float4 w2v = *(const float4*)(w + d*4 + 8);
    float4 w3v = *(const float4*)(w + d*4 + 12);
    const uint2* xp = (const uint2*)x + q;
    uint2 raw = xp[0];
    float2 xa = __half22float2(*(__half2*)&raw.x);
    float2 xb = __half22float2(*(__half2*)&raw.y);
    float a0 = w0v.w * xa.x, a1 = w1v.w * xa.y, a2 = w2v.w * xb.x, a3 = w3v.w * xb.y;
    if (l >= 1) {
        uint2 t = xp[-(DD/4)];
        float2 ta = __half22float2(*(__half2*)&t.x);
        float2 tb = __half22float2(*(__half2*)&t.y);
        a0 += w0v.z*ta.x; a1 += w1v.z*ta.y; a2 += w2v.z*tb.x; a3 += w3v.z*tb.y;
    }
    if (l >= 2) {
        uint2 t = xp[-(DD/2)];
        float2 ta = __half22float2(*(__half2*)&t.x);
        float2 tb = __half22float2(*(__half2*)&t.y);
        a0 += w0v.y*ta.x; a1 += w1v.y*ta.y; a2 += w2v.y*tb.x; a3 += w3v.y*tb.y;
    }
    if (l >= 3) {
        uint2 t = xp[-(3*DD/4)];
        float2 ta = __half22float2(*(__half2*)&t.x);
        float2 tb = __half22float2(*(__half2*)&t.y);
        a0 += w0v.x*ta.x; a1 += w1v.x*ta.y; a2 += w2v.x*tb.x; a3 += w3v.x*tb.y;
    }
    a0 = a0 / (1.f + __expf(-a0));
    a1 = a1 / (1.f + __expf(-a1));
    a2 = a2 / (1.f + __expf(-a2));
    a3 = a3 / (1.f + __expf(-a3));
    __half2 o0 = __floats2half2_rn(a0, a1);
    __half2 o1 = __floats2half2_rn(a2, a3);
    uint2 ov = {*(unsigned*)&o0, *(unsigned*)&o1};
    ((uint2*)y)[q] = ov;
}

// ------------------- beta = sigmoid(hs_h @ Wb^T) (fp16 hs) ------------------
__global__ __launch_bounds__(128) void beta_kernel(const float* __restrict__ Wb)
{
    __shared__ float red[4][128];
    int n = blockIdx.x, tid = threadIdx.x;
    const __half* hr = g_hs_h + (size_t)n * DD;
    float s0=0,s1=0,s2=0,s3=0;
    for (int i = tid*2; i < DD; i += 256) {
        float2 x = __half22float2(*(const __half2*)&hr[i]);
        s0 += x.x * Wb[i]        + x.y * Wb[i+1];
        s1 += x.x * Wb[DD + i]   + x.y * Wb[DD + i+1];
        s2 += x.x * Wb[2*DD + i] + x.y * Wb[2*DD + i+1];
        s3 += x.x * Wb[3*DD + i] + x.y * Wb[3*DD + i+1];
    }
    red[0][tid]=s0; red[1][tid]=s1; red[2][tid]=s2; red[3][tid]=s3;
    __syncthreads();
    for (int st = 64; st > 0; st >>= 1) {
        if (tid < st)
#pragma unroll
            for (int h = 0; h < 4; h++) red[h][tid] += red[h][tid + st];
        __syncthreads();
    }
    if (tid < 4) g_beta[(size_t)n*HH + tid] = 1.f / (1.f + expf(-red[tid][0]));
}

// ---------------- per-chunk delta-rule precompute (tensor-core mma) ---------
#define PSTR 264
#define PSMEM ((2*32*PSTR + 32*33 + 32*36 + 96) * 4)
__global__ __launch_bounds__(256) void precompute_kernel()
{
    extern __shared__ float psm[];
    float*    Kt  = psm;
    float*    Qt  = Kt + 32*PSTR;
    float*    Am  = Qt + 32*PSTR;
    unsigned* Ttf = (unsigned*)(Am + 32*33);
    float*    bet = (float*)(Ttf + 32*36);
    float*    rnk = bet + 32;
    float*    rnq = rnk + 32;

    int blk = blockIdx.x;
    int c  = blk % NC;
    int bh = blk / NC;
    int h  = bh % HH;
    int b  = bh / HH;
    int tid = threadIdx.x;
    int l0 = c * 32;
    int wid = tid >> 5, lane = tid & 31;
    int lr = lane >> 2, lk = lane & 3;

    for (int e = tid*4; e < 32*256; e += 1024) {
        int r = e >> 8, d = e & 255;
        size_t gb = ((size_t)(b*LL + l0 + r))*DD + h*DV + d;
        uint2 kh = *(const uint2*)&g_kc_h[gb];
        float2 ka = __half22float2(*(__half2*)&kh.x);
        float2 kb2 = __half22float2(*(__half2*)&kh.y);
        *(float4*)&Kt[r*PSTR + d] = make_float4(ka.x, ka.y, kb2.x, kb2.y);
        uint2 qh = *(const uint2*)&g_qc_h[gb];
        float2 qa = __half22float2(*(__half2*)&qh.x);
        float2 qb2 = __half22float2(*(__half2*)&qh.y);
        *(float4*)&Qt[r*PSTR + d] = make_float4(qa.x, qa.y, qb2.x, qb2.y);
    }
    if (tid < 32) bet[tid] = g_beta[((size_t)(b*LL + l0 + tid))*HH + h];
    __syncthreads();

    {
        int r = tid >> 3, part = tid & 7;
        float sk = 0.f, sq = 0.f;
        for (int j = part*32; j < part*32 + 32; j++) {
            float x = Kt[r*PSTR + j]; sk += x*x;
            float y = Qt[r*PSTR + j]; sq += y*y;
        }
        sk += __shfl_down_sync(0xffffffffu, sk, 4, 8);
        sk += __shfl_down_sync(0xffffffffu, sk, 2, 8);
        sk += __shfl_down_sync(0xffffffffu, sk, 1, 8);
        sq += __shfl_down_sync(0xffffffffu, sq, 4, 8);
        sq += __shfl_down_sync(0xffffffffu, sq, 2, 8);
        sq += __shfl_down_sync(0xffffffffu, sq, 1, 8);
        if (part == 0) { rnk[r] = rsqrtf(sk + 1e-6f); rnq[r] = rsqrtf(sq + 1e-6f); }
    }
    __syncthreads();

    size_t obase = (size_t)blk * (32*256);
    for (int e = tid*4; e < 32*256; e += 1024) {
        int r = e >> 8, d = e & 255;
        float rk = rnk[r], rq = rnq[r];
        float4 kv = *(float4*)&Kt[r*PSTR + d];
        kv.x *= rk; kv.y *= rk; kv.z *= rk; kv.w *= rk;
        unsigned* kd = (unsigned*)&Kt[r*PSTR + d];
        kd[0]=f2tf(kv.x); kd[1]=f2tf(kv.y); kd[2]=f2tf(kv.z); kd[3]=f2tf(kv.w);
        float4 qv = *(float4*)&Qt[r*PSTR + d];
        qv.x *= rq; qv.y *= rq; qv.z *= rq; qv.w *= rq;
        __half2 qh0 = __floats2half2_rn(qv.x, qv.y);
        __half2 qh1 = __floats2half2_rn(qv.z, qv.w);
        uint2 qo = {*(unsigned*)&qh0, *(unsigned*)&qh1};
        *(uint2*)&g_qn_h[obase + e] = qo;
        unsigned* qd = (unsigned*)&Qt[r*PSTR + d];
        qd[0]=f2tf(qv.x); qd[1]=f2tf(qv.y); qd[2]=f2tf(qv.z); qd[3]=f2tf(qv.w);
    }
    __syncthreads();

    for (int e = tid*2; e < 32*256; e += 512) {
        int r = e & 31, d = e >> 5;
        float v0 = Kt[r*PSTR + d];
        float v1 = Kt[(r+1)*PSTR + d];
        *(__half2*)&g_knT_h[obase + e] = __floats2half2_rn(v0, v1);
    }

    {
        int m0 = (wid >> 2) * 16, n0 = (wid & 3) * 8;
        const unsigned* Ku = (const unsigned*)Kt;
        const unsigned* Qu = (const unsigned*)Qt;
        float accA[4] = {0,0,0,0}, accQ[4] = {0,0,0,0};
#pragma unroll 4
        for (int kb = 0; kb < 256; kb += 8) {
            unsigned ak[4], aq[4], bf[2];
            ak[0] = Ku[(m0+lr)*PSTR + kb+lk];
            ak[1] = Ku[(m0+lr+8)*PSTR + kb+lk];
            ak[2] = Ku[(m0+lr)*PSTR + kb+lk+4];
            ak[3] = Ku[(m0+lr+8)*PSTR + kb+lk+4];
            aq[0] = Qu[(m0+lr)*PSTR + kb+lk];
            aq[1] = Qu[(m0+lr+8)*PSTR + kb+lk];
            aq[2] = Qu[(m0+lr)*PSTR + kb+lk+4];
            aq[3] = Qu[(m0+lr+8)*PSTR + kb+lk+4];
            bf[0] = Ku[(n0+lr)*PSTR + kb+lk];
            bf[1] = Ku[(n0+lr)*PSTR + kb+lk+4];
            mma_tf32(accA, ak, bf);
            mma_tf32(accQ, aq, bf);
        }
        size_t abase = (size_t)blk * 1024;
        int r0 = m0 + lr, r1 = r0 + 8, c0 = n0 + 2*lk, c1 = c0 + 1;
        float q00 = (c0 <= r0) ? accQ[0] : 0.f;
        float q01 = (c1 <= r0) ? accQ[1] : 0.f;
        float q10 = (c0 <= r1) ? accQ[2] : 0.f;
        float q11 = (c1 <= r1) ? accQ[3] : 0.f;
        *(__half2*)&g_attn_h[abase + r0*32 + c0] = __floats2half2_rn(q00, q01);
        *(__half2*)&g_attn_h[abase + r1*32 + c0] = __floats2half2_rn(q10, q11);
        Am[r0*33 + c0] = (c0 < r0) ? -bet[r0]*accA[0] : 0.f;
        Am[r0*33 + c1] = (c1 < r0) ? -bet[r0]*accA[1] : 0.f;
        Am[r1*33 + c0] = (c0 < r1) ? -bet[r1]*accA[2] : 0.f;
        Am[r1*33 + c1] = (c1 < r1) ? -bet[r1]*accA[3] : 0.f;
    }
    __syncthreads();

    if (tid < 32) {
        int ln = tid;
        for (int i = 1; i < 32; i++) {
            float t = 0.f;
            if (ln < i) for (int p = 0; p < i; p++) t += Am[i*33 + p] * Am[p*33 + ln];
            __syncwarp();
            if (ln < i) Am[i*33 + ln] += t;
            __syncwarp();
        }
    }
    __syncthreads();
    for (int e = tid; e < 1024; e += 256) {
        int i = e >> 5, j = e & 31;
        float t = Am[i*33 + j] + (i == j ? 1.f : 0.f);
        Ttf[i*36 + j] = f2tf(t * bet[j]);
    }
    __syncthreads();
    for (int e = tid*4; e < 32*256; e += 1024) {
        int r = e >> 8, d = e & 255;
        uint2 vh = *(const uint2*)&g_vc_h[((size_t)(b*LL + l0 + r))*DD + h*DV + d];
        float2 va = __half22float2(*(__half2*)&vh.x);
        float2 vb2 = __half22float2(*(__half2*)&vh.y);
        unsigned* qd = (unsigned*)&Qt[r*PSTR + d];
        qd[0]=f2tf(va.x); qd[1]=f2tf(va.y); qd[2]=f2tf(vb2.x); qd[3]=f2tf(vb2.y);
    }
    __syncthreads();

    {
        int m0 = (wid & 1) * 16;
        int nb = (wid >> 1) * 64;
        const unsigned* Ku = (const unsigned*)Kt;
        const unsigned* Vu = (const unsigned*)Qt;
        unsigned a[4][4];
#pragma unroll
        for (int kk = 0; kk < 4; kk++) {
            int kb = kk*8;
            a[kk][0] = Ttf[(m0+lr)*36 + kb+lk];
            a[kk][1] = Ttf[(m0+lr+8)*36 + kb+lk];
            a[kk][2] = Ttf[(m0+lr)*36 + kb+lk+4];
            a[kk][3] = Ttf[(m0+lr+8)*36 + kb+lk+4];
        }
#pragma unroll
        for (int nt = 0; nt < 8; nt++) {
            int n0 = nb + nt*8;
            float au[4] = {0,0,0,0}, aw[4] = {0,0,0,0};
#pragma unroll
            for (int kk = 0; kk < 4; kk++) {
                int kb = kk*8;
                unsigned bu[2], bw[2];
                bu[0] = Vu[(kb+lk)*PSTR + n0+lr];
                bu[1] = Vu[(kb+lk+4)*PSTR + n0+lr];
                bw[0] = Ku[(kb+lk)*PSTR + n0+lr];
                bw[1] = Ku[(kb+lk+4)*PSTR + n0+lr];
                mma_tf32(au, a[kk], bu);
                mma_tf32(aw, a[kk], bw);
            }
            int r0 = m0 + lr, r1 = r0 + 8, cc = n0 + 2*lk;
            *(__half2*)&g_u_h[obase + r0*256 + cc] = __floats2half2_rn(au[0], au[1]);
            *(__half2*)&g_u_h[obase + r1*256 + cc] = __floats2half2_rn(au[2], au[3]);
            *(__half2*)&g_w_h[obase + r0*256 + cc] = __floats2half2_rn(aw[0], aw[1]);
            *(__half2*)&g_w_h[obase + r1*256 + cc] = __floats2half2_rn(aw[2], aw[3]);
        }
    }
}

// --------- sequential inter-chunk scan (fp16 mma, cp.async dbl-buffer) ------
// Per-chunk inputs (w,q,kT tiles + u slice + attn) staged via cp.async with
// chunk-level double buffering; chunk c+1 loads overlap chunk c's GEMMs.
#define BUF_W  0
#define BUF_Q  16896
#define BUF_KT 33792
#define BUF_U  54272        // [32][40] halves (20-word rows)
#define BUF_AT 56832        // [32][40] halves
#define BUF_SIZE 59392
#define SF_OFF 118784       // float [256][40]
#define SH_OFF 159744       // [32][132] words (fp16 S^T shadow)
#define UH_OFF 176640       // [32][20] words (u_i^T fp16)
#define SCAN_SMEM 179200

#define SLOAD(cc, st) do {                                                     \
    size_t base_ = ((size_t)bh*NC + (cc)) * (32*256);                          \
    size_t abase_ = ((size_t)bh*NC + (cc)) * 1024;                             \
    unsigned bb_ = smb + (unsigned)((st)*BUF_SIZE);                            \
    _Pragma("unroll")                                                          \
    for (int i_ = 0; i_ < 4; i_++) {                                           \
        int e_ = (tid + i_*256) * 8;                                           \
        int r_ = e_ >> 8, j_ = e_ & 255;                                       \
        unsigned d_ = (unsigned)(r_*264 + j_) * 2;                             \
        asm volatile("cp.async.cg.shared.global [%0], [%1], 16;"               \
            :: "r"(bb_ + BUF_W + d_), "l"(&g_w_h[base_ + e_]));                \
        asm volatile("cp.async.cg.shared.global [%0], [%1], 16;"               \
            :: "r"(bb_ + BUF_Q + d_), "l"(&g_qn_h[base_ + e_]));               \
        int r2_ = e_ >> 5, j2_ = e_ & 31;                                      \
        asm volatile("cp.async.cg.shared.global [%0], [%1], 16;"               \
            :: "r"(bb_ + BUF_KT + (unsigned)(r2_*40 + j2_)*2),                 \
               "l"(&g_knT_h[base_ + e_]));                                     \
    }                                                                          \
    if (tid < 128) {                                                           \
        int e_ = tid * 8;                                                      \
        int r_ = e_ >> 5, j_ = e_ & 31;                                        \
        asm volatile("cp.async.cg.shared.global [%0], [%1], 16;"               \
            :: "r"(bb_ + BUF_U + (unsigned)(r_*40 + j_)*2),                    \
               "l"(&g_u_h[base_ + r_*256 + g*32 + j_]));                       \
    } else {                                                                   \
        int e_ = (tid - 128) * 8;                                              \
        int r_ = e_ >> 5, j_ = e_ & 31;                                        \
        asm volatile("cp.async.cg.shared.global [%0], [%1], 16;"               \
            :: "r"(bb_ + BUF_AT + (unsigned)(r_*40 + j_)*2),                   \
               "l"(&g_attn_h[abase_ + e_]));                                   \
    }                                                                          \
} while (0)

__global__ __launch_bounds__(256) void scan_kernel()
{
    extern __shared__ char ssm[];
    float*    Sf  = (float*)(ssm + SF_OFF);
    unsigned* Sh  = (unsigned*)(ssm + SH_OFF);
    unsigned* Uh  = (unsigned*)(ssm + UH_OFF);
    __half*   ShH = (__half*)Sh;
    __half*   UhH = (__half*)Uh;
    unsigned smb;
    asm("{ .reg .u64 t; cvta.to.shared.u64 t, %1; cvt.u32.u64 %0, t; }"
        : "=r"(smb) : "l"(ssm));

    int blk = blockIdx.x;
    int g  = blk & (NG-1);
    int bh = blk >> 3;
    int b  = bh >> 2;
    int h  = bh & 3;
    int tid = threadIdx.x;
    int wid = tid >> 5, lane = tid & 31;
    int lr = lane >> 2, lk = lane & 3;
    int m0 = (wid >> 2) * 16;
    int n0 = (wid & 3) * 8;

    for (int e = tid; e < 256*40; e += 256) Sf[e] = 0.f;
    for (int e = tid; e < 32*132; e += 256) Sh[e] = 0u;
    __syncthreads();

    SLOAD(0, 0);
    asm volatile("cp.async.commit_group;");

    for (int c = 0; c < NC; c++) {
        asm volatile("cp.async.wait_group 0;");
        __syncthreads();
        if (c + 1 < NC) SLOAD(c + 1, (c + 1) & 1);
        asm volatile("cp.async.commit_group;");

        int st = c & 1;
        const unsigned* Wt = (const unsigned*)(ssm + st*BUF_SIZE + BUF_W);
        const unsigned* Qt = (const unsigned*)(ssm + st*BUF_SIZE + BUF_Q);
        const unsigned* Kt = (const unsigned*)(ssm + st*BUF_SIZE + BUF_KT);
        const __half*   Ub = (const __half*)(ssm + st*BUF_SIZE + BUF_U);
        const unsigned* Ab = (const unsigned*)(ssm + st*BUF_SIZE + BUF_AT);

        // (1) u_i = u - w@S    (32x32, K=256, fp16)
        {
            float acc[4] = {0.f, 0.f, 0.f, 0.f};
#pragma unroll 4
            for (int kb = 0; kb < 256; kb += 16) {
                int kw = (kb >> 1) + lk;
                unsigned a[4], bf[2];
                a[0] = Wt[(m0+lr)*132 + kw];
                a[1] = Wt[(m0+lr+8)*132 + kw];
                a[2] = Wt[(m0+lr)*132 + kw + 4];
                a[3] = Wt[(m0+lr+8)*132 + kw + 4];
                bf[0] = Sh[(n0+lr)*132 + kw];
                bf[1] = Sh[(n0+lr)*132 + kw + 4];
                mma_f16(acc, a, bf);
            }
            int r0 = m0 + lr, r1 = r0 + 8, cb = n0 + 2*lk;
            float u0 = __half2float(Ub[r0*40 + cb])   - acc[0];
            float u1 = __half2float(Ub[r0*40 + cb+1]) - acc[1];
            float u2 = __half2float(Ub[r1*40 + cb])   - acc[2];
            float u3 = __half2float(Ub[r1*40 + cb+1]) - acc[3];
            UhH[cb*40 + r0]     = __float2half_rn(u0);
            UhH[(cb+1)*40 + r0] = __float2half_rn(u1);
            UhH[cb*40 + r1]     = __float2half_rn(u2);
            UhH[(cb+1)*40 + r1] = __float2half_rn(u3);
        }
        __syncthreads();

        // (2) o = q@S + attn@u_i  -> g_delta (fp16)
        {
            float acc[4] = {0.f, 0.f, 0.f, 0.f};
#pragma unroll 4
            for (int kb = 0; kb < 256; kb += 16) {
                int kw = (kb >> 1) + lk;
                unsigned a[4], bf[2];
                a[0] = Qt[(m0+lr)*132 + kw];
                a[1] = Qt[(m0+lr+8)*132 + kw];
                a[2] = Qt[(m0+lr)*132 + kw + 4];
                a[3] = Qt[(m0+lr+8)*132 + kw + 4];
                bf[0] = Sh[(n0+lr)*132 + kw];
                bf[1] = Sh[(n0+lr)*132 + kw + 4];
                mma_f16(acc, a, bf);
            }
#pragma unroll
            for (int kb = 0; kb < 32; kb += 16) {
                int kw = (kb >> 1) + lk;
                unsigned a[4], bf[2];
                a[0] = Ab[(m0+lr)*20 + kw];
                a[1] = Ab[(m0+lr+8)*20 + kw];
                a[2] = Ab[(m0+lr)*20 + kw + 4];
                a[3] = Ab[(m0+lr+8)*20 + kw + 4];
                bf[0] = Uh[(n0+lr)*20 + kw];
                bf[1] = Uh[(n0+lr)*20 + kw + 4];
                mma_f16(acc, a, bf);
            }
            size_t ob = ((size_t)(b*LL + c*32 + m0 + lr))*DD + h*DV + g*32 + n0 + 2*lk;
            *(__half2*)&g_delta_h[ob]        = __floats2half2_rn(acc[0], acc[1]);
            *(__half2*)&g_delta_h[ob + 8*DD] = __floats2half2_rn(acc[2], acc[3]);
        }
        __syncthreads();

        // (3) S += k^T @ u_i
#pragma unroll
        for (int t = 0; t < 2; t++) {
            int tm = (wid*2 + t) * 16;
#pragma unroll
            for (int tn = 0; tn < 4; tn++) {
                int nn = tn*8;
                int r0 = tm + lr, r1 = r0 + 8, cb = nn + 2*lk;
                float acc[4];
                acc[0] = Sf[r0*40+cb]; acc[1] = Sf[r0*40+cb+1];
                acc[2] = Sf[r1*40+cb]; acc[3] = Sf[r1*40+cb+1];
#pragma unroll
                for (int kb = 0; kb < 32; kb += 16) {
                    int kw = (kb >> 1) + lk;
                    unsigned a[4], bf[2];
                    a[0] = Kt[(tm+lr)*20 + kw];
                    a[1] = Kt[(tm+lr+8)*20 + kw];
                    a[2] = Kt[(tm+lr)*20 + kw + 4];
                    a[3] = Kt[(tm+lr+8)*20 + kw + 4];
                    bf[0] = Uh[(nn+lr)*20 + kw];
                    bf[1] = Uh[(nn+lr)*20 + kw + 4];
                    mma_f16(acc, a, bf);
                }
                Sf[r0*40+cb] = acc[0]; Sf[r0*40+cb+1] = acc[1];
                Sf[r1*40+cb] = acc[2]; Sf[r1*40+cb+1] = acc[3];
                ShH[cb*264 + r0]     = __float2half_rn(acc[0]);
                ShH[(cb+1)*264 + r0] = __float2half_rn(acc[1]);
                ShH[cb*264 + r1]     = __float2half_rn(acc[2]);
                ShH[(cb+1)*264 + r1] = __float2half_rn(acc[3]);
            }
        }
        __syncthreads();
    }
}

// ------------------- per-(head,channel) FIR conv (fp16 io) ------------------
template<int K>
__global__ __launch_bounds__(256) void fir_kernel(
    const float* __restrict__ fw, __half* __restrict__ y)
{
    __shared__ float2 vbuf[(128 + K - 1) * 16];
    __shared__ float2 wbuf[16 * K];
    int bh = blockIdx.x;
    int b = bh / HH, h = bh % HH;
    int l0 = blockIdx.y * 128;
    int d0 = blockIdx.z * 32;
    int tid = threadIdx.x;

    for (int idx = tid; idx < 16*K; idx += 256) {
        int dp = idx / K, t = idx % K;
        float2 wv;
        wv.x = fw[(size_t)(h*DV + d0 + 2*dp)*K + t];
        wv.y = fw[(size_t)(h*DV + d0 + 2*dp + 1)*K + t];
        wbuf[dp*K + t] = wv;
    }
    for (int idx = tid; idx < (128 + K - 1)*16; idx += 256) {
        int lrr = idx >> 4, dp = idx & 15;
        int l = l0 - (K - 1) + lrr;
        vbuf[idx] = (l >= 0)
            ? __half22float2(*(const __half2*)&g_vc_h[((size_t)(b*LL + l))*DD + h*DV + d0 + 2*dp])
            : make_float2(0.f, 0.f);
    }
    __syncthreads();

    int dp = tid & 15;
    int lr0 = (tid >> 4) * 8;
    for (int m = 0; m < 8; m++) {
        int lrr = lr0 + m;
        float2 acc = {0.f, 0.f};
#pragma unroll
        for (int t = 0; t < K; t++) {
            float2 v = vbuf[(lrr + t)*16 + dp];
            float2 wv = wbuf[dp*K + t];
            acc.x = fmaf(v.x, wv.x, acc.x);
            acc.y = fmaf(v.y, wv.y, acc.y);
        }
        *(__half2*)&y[((size_t)(b*LL + l0 + lrr))*DD + h*DV + d0 + 2*dp]
            = __floats2half2_rn(acc.x, acc.y);
    }
}

// ------------- gate input assembly (hs + stats), stored as fp16 -------------
__global__ __launch_bounds__(256) void stats_kernel(const float* __restrict__ hs)
{
    int n = blockIdx.x, tid = threadIdx.x;
    {
        int i = tid * 4;
        float4 v = *(const float4*)&hs[(size_t)n*DD + i];
        __half2 lo = __floats2half2_rn(v.x, v.y);
        __half2 hi = __floats2half2_rn(v.z, v.w);
        uint2 o = {*(unsigned*)&lo, *(unsigned*)&hi};
        *(uint2*)&g_gatein_h[(size_t)n*GINP + i] = o;
    }
    if (tid < 32) g_gatein_h[(size_t)n*GINP + GIN + tid] = __float2half_rn(0.f);
    int warp = tid >> 5, lane = tid & 31;
    for (int rep = 0; rep < 2; rep++) {
        int combo = warp*2 + rep;
        int path = combo >> 2, h = combo & 3;
        const __half* p;
        if      (path == 0) p = g_short_h;
        else if (path == 1) p = g_long_h;
        else if (path == 2) p = g_delta_h;
        else                p = g_vc_h;
        p += (size_t)n*DD + h*DV;
        float s1 = 0.f, s2 = 0.f;
        for (int j = lane; j < 256; j += 32) {
            float x = __half2float(p[j]); s1 += x; s2 += x*x;
        }
#pragma unroll
        for (int st = 16; st > 0; st >>= 1) {
            s1 += __shfl_down_sync(0xffffffffu, s1, st);
            s2 += __shfl_down_sync(0xffffffffu, s2, st);
        }
        if (lane == 0) {
            float m  = s1 * (1.f/256.f);
            float va = s2 * (1.f/256.f) - m*m;
            g_gatein_h[(size_t)n*GINP + DD + path*8 + h*2]     = __float2half_rn(m);
            g_gatein_h[(size_t)n*GINP + DD + path*8 + h*2 + 1] = __float2half_rn(va);
        }
    }
}

// ------------------- gate2 + softmax + floor (fp16 hmid) --------------------
__global__ __launch_bounds__(256) void gate2_kernel(
    const float* __restrict__ w2, const float* __restrict__ log_temp,
    const float* __restrict__ base_bias, const float* __restrict__ floor_raw)
{
    __shared__ float hrow[HID];
    __shared__ float lg[16];
    int n = blockIdx.x, tid = threadIdx.x;
    for (int i = tid*2; i < HID; i += 512) {
        float2 v = __half22float2(*(const __half2*)&g_hmid_h[(size_t)n*HID + i]);
        hrow[i] = v.x; hrow[i+1] = v.y;
    }
    __syncthreads();
    int warp = tid >> 5, lane = tid & 31;
    for (int rep = 0; rep < 2; rep++) {
        int o = warp*2 + rep;
        const float* wr = w2 + (size_t)o*HID;
        float s = 0.f;
        for (int i = lane; i < HID; i += 32) s = fmaf(hrow[i], wr[i], s);
#pragma unroll
        for (int st = 16; st > 0; st >>= 1) s += __shfl_down_sync(0xffffffffu, s, st);
        if (lane == 0) lg[o] = s;
    }
    __syncthreads();
    if (tid < 4) {
        int h = tid;
        float temp = log1pf(expf(log_temp[h])) + 1e-4f;
        float z[4], m = -1e30f;
#pragma unroll
        for (int i = 0; i < 4; i++) {
            z[i] = (lg[h*4+i] + base_bias[h*4+i]) / temp;
            m = fmaxf(m, z[i]);
        }
        float e[4], s = 0.f;
#pragma unroll
        for (int i = 0; i < 4; i++) { e[i] = expf(z[i] - m); s += e[i]; }
        float p[4], s2 = 0.f;
#pragma unroll
        for (int i = 0; i < 4; i++) {
            p[i] = e[i] / s;
            float f = 0.05f / (1.f + expf(-floor_raw[h*4+i]));
            p[i] = fmaxf(p[i], f);
            s2 += p[i];
        }
#pragma unroll
        for (int i = 0; i < 4; i++) g_probs[(size_t)n*16 + h*4 + i] = p[i] / s2;
    }
}

// ------------- path mix + RMS norm, output stored as fp16 -------------------
__global__ __launch_bounds__(256) void mix_kernel(const float* __restrict__ onorm)
{
    __shared__ float pr[16];
    __shared__ float wsum[8];
    int n = blockIdx.x, tid = threadIdx.x;
    if (tid < 16) pr[tid] = g_probs[(size_t)n*16 + tid];
    __syncthreads();
    int h = tid >> 6;
    int dd = (tid & 63) * 4;
    size_t pb = (size_t)n*DD + h*DV + dd;
    uint2 sraw = *(const uint2*)&g_short_h[pb];
    uint2 lraw = *(const uint2*)&g_long_h[pb];
    uint2 draw = *(const uint2*)&g_delta_h[pb];
    uint2 vraw = *(const uint2*)&g_vc_h[pb];
    float2 sa = __half22float2(*(__half2*)&sraw.x), sb = __half22float2(*(__half2*)&sraw.y);
    float2 la = __half22float2(*(__half2*)&lraw.x), lb = __half22float2(*(__half2*)&lraw.y);
    float2 da = __half22float2(*(__half2*)&draw.x), db = __half22float2(*(__half2*)&draw.y);
    float2 va = __half22float2(*(__half2*)&vraw.x), vb = __half22float2(*(__half2*)&vraw.y);
    float p0 = pr[h*4+0], p1 = pr[h*4+1], p2 = pr[h*4+2], p3 = pr[h*4+3];
    float o[4];
    o[0] = p0*sa.x + p1*la.x + p2*da.x + p3*va.x;
    o[1] = p0*sa.y + p1*la.y + p2*da.y + p3*va.y;
    o[2] = p0*sb.x + p1*lb.x + p2*db.x + p3*vb.x;
    o[3] = p0*sb.y + p1*lb.y + p2*db.y + p3*vb.y;
    float ss = o[0]*o[0] + o[1]*o[1] + o[2]*o[2] + o[3]*o[3];
#pragma unroll
    for (int st = 16; st > 0; st >>= 1) ss += __shfl_down_sync(0xffffffffu, ss, st);
    int warp = tid >> 5, lane = tid & 31;
    if (lane == 0) wsum[warp] = ss;
    __syncthreads();
    float tot = wsum[h*2] + wsum[h*2+1];
    float scale = rsqrtf(tot * (1.f/256.f) + 1e-5f);
    __half2 h0 = __floats2half2_rn(o[0]*scale*onorm[dd],   o[1]*scale*onorm[dd+1]);
    __half2 h1 = __floats2half2_rn(o[2]*scale*onorm[dd+2], o[3]*scale*onorm[dd+3]);
    uint2 pk = {*(unsigned*)&h0, *(unsigned*)&h1};
    *(uint2*)&g_mix_h[pb] = pk;
}

// ------------------------- launch ------------------------------------------
extern "C" void kernel_launch(void* const* d_in, const int* in_sizes, int n_in,
                              void* d_out, int out_size)
{
    const float* hs        = (const float*)d_in[0];
    const float* Wq        = (const float*)d_in[1];
    const float* Wk        = (const float*)d_in[2];
    const float* Wv        = (const float*)d_in[3];
    const float* Wb        = (const float*)d_in[4];
    const float* qconv_w   = (const float*)d_in[5];
    const float* kconv_w   = (const float*)d_in[6];
    const float* vconv_w   = (const float*)d_in[7];
    const float* fir_s     = (const float*)d_in[8];
    const float* fir_l     = (const float*)d_in[9];
    const float* gate_w1   = (const float*)d_in[10];
    const float* gate_b1   = (const float*)d_in[11];
    const float* gate_w2   = (const float*)d_in[12];
    const float* log_temp  = (const float*)d_in[13];
    const float* base_bias = (const float*)d_in[14];
    const float* floor_raw = (const float*)d_in[15];
    const float* onorm_w   = (const float*)d_in[16];
    const float* Wo        = (const float*)d_in[17];
    float* out = (float*)d_out;

    void *p_qlin, *p_klin, *p_vlin, *p_qc, *p_kc, *p_vc, *p_hmid, *p_short, *p_long;
    void *p_hsh, *p_wqh, *p_wkh, *p_wvh, *p_woh, *p_gw1h, *p_gateinh, *p_mixh;
    cudaGetSymbolAddress(&p_qlin, g_qlin_h);
    cudaGetSymbolAddress(&p_klin, g_klin_h);
    cudaGetSymbolAddress(&p_vlin, g_vlin_h);
    cudaGetSymbolAddress(&p_qc, g_qc_h);
    cudaGetSymbolAddress(&p_kc, g_kc_h);
    cudaGetSymbolAddress(&p_vc, g_vc_h);
    cudaGetSymbolAddress(&p_hmid, g_hmid_h);
    cudaGetSymbolAddress(&p_short, g_short_h);
    cudaGetSymbolAddress(&p_long, g_long_h);
    cudaGetSymbolAddress(&p_hsh, g_hs_h);
    cudaGetSymbolAddress(&p_wqh, g_wq_h);
    cudaGetSymbolAddress(&p_wkh, g_wk_h);
    cudaGetSymbolAddress(&p_wvh, g_wv_h);
    cudaGetSymbolAddress(&p_woh, g_wo_h);
    cudaGetSymbolAddress(&p_gw1h, g_gw1_h);
    cudaGetSymbolAddress(&p_gateinh, g_gatein_h);
    cudaGetSymbolAddress(&p_mixh, g_mix_h);

    cudaFuncSetAttribute(scan_kernel,
        cudaFuncAttributeMaxDynamicSharedMemorySize, SCAN_SMEM);
    cudaFuncSetAttribute(precompute_kernel,
        cudaFuncAttributeMaxDynamicSharedMemorySize, PSMEM);
    cudaFuncSetAttribute(hgemm,
        cudaFuncAttributeMaxDynamicSharedMemorySize, HGEMM_SMEM);

    dim3 blk(256);

    // 0. pre-convert hs + weights to fp16 (gate_w1 padded separately)
    cvt_h6<<<dim3(NROW*DD/1024, 6), blk>>>(
        hs, (__half*)p_hsh, NROW*DD,
        Wq, (__half*)p_wqh, DD*DD,
        Wk, (__half*)p_wkh, DD*DD,
        Wv, (__half*)p_wvh, DD*DD,
        Wo, (__half*)p_woh, DD*DD,
        nullptr, nullptr, 0);
    cvt_gw1pad<<<(HID*GINP/4 + 255)/256, blk>>>(gate_w1);

    // q/k/v projections — fp16 outputs (mode 2)
    hgemm<<<dim3(DD/128, NROW/128, 3), blk, HGEMM_SMEM>>>(
        (const __half*)p_hsh,
        (const __half*)p_wqh, (const __half*)p_wkh, (const __half*)p_wvh,
        (float*)p_qlin, (float*)p_klin, (float*)p_vlin,
        nullptr, NROW, DD, DD, 2);

    // causal conv4 + SiLU (fp16 io, 4 elems/thread)
    conv4_silu3<<<dim3(NROW*DD/1024, 3), blk>>>(
        (const __half*)p_qlin, (const __half*)p_klin, (const __half*)p_vlin,
        qconv_w, kconv_w, vconv_w,
        (__half*)p_qc, (__half*)p_kc, (__half*)p_vc);

    // beta (reads fp16 hs)
    beta_kernel<<<NROW, 128>>>(Wb);

    // delta-rule
    precompute_kernel<<<BB*HH*NC, blk, PSMEM>>>();
    scan_kernel<<<BB*HH*NG, blk, SCAN_SMEM>>>();

    // FIR paths
    fir_kernel<3><<<dim3(BB*HH, LL/128, DV/32), blk>>>(fir_s, (__half*)p_short);
    fir_kernel<63><<<dim3(BB*HH, LL/128, DV/32), blk>>>(fir_l, (__half*)p_long);

    // gate (hmid fp16: mode 1|2 = GELU + fp16 out)
    stats_kernel<<<NROW, blk>>>(hs);
    hgemm<<<dim3(HID/128, NROW/128, 1), blk, HGEMM_SMEM>>>(
        (const __half*)p_gateinh,
        (const __half*)p_gw1h, nullptr, nullptr,
        (float*)p_hmid, nullptr, nullptr,
        gate_b1, NROW, HID, GINP, 3);
    gate2_kernel<<<NROW, blk>>>(gate_w2, log_temp, base_bias, floor_raw);

    // mix + RMS norm
    mix_kernel<<<NROW, blk>>>(onorm_w);

    // output projection (fp32 out)
    hgemm<<<dim3(DD/128, NROW/128, 1), blk, HGEMM_SMEM>>>(
        (const __half*)p_mixh,
        (const __half*)p_woh, nullptr, nullptr,
        out, nullptr, nullptr,
        nullptr, NROW, DD, DD, 0);
}

// round 17
// speedup vs baseline: 1.4276x; 1.0236x over previous
#include <cuda_runtime.h>
#include <cuda_fp16.h>
#include <math.h>
#include <stdint.h>

#define BB 2
#define LL 2048
#define DD 1024
#define HH 4
#define DV 256
#define CKN 32
#define NC 64              // LL / CKN
#define NROW (BB*LL)       // 4096
#define GIN 1056
#define GINP 1088          // padded to multiple of 64
#define HID 2048
#define NG 8               // Dv groups of 32 in the scan

// ------------------------- scratch (device globals) -------------------------
__device__ float g_beta[NROW*HH];
__device__ float g_probs[NROW*16];
// fp16 intermediates + GEMM operands
__device__ __half g_qn_h[NROW*DD];       // [bh][c][time32][dv256]
__device__ __half g_knT_h[NROW*DD];      // [bh][c][dv256][time32]
__device__ __half g_u_h[NROW*DD];        // [bh][c][time32][dv256]
__device__ __half g_w_h[NROW*DD];        // [bh][c][time32][dv256]
__device__ __half g_attn_h[BB*HH*NC*CKN*CKN];
__device__ __half g_delta_h[NROW*DD];
__device__ __half g_short_h[NROW*DD];
__device__ __half g_long_h[NROW*DD];
__device__ __half g_hmid_h[NROW*HID];
__device__ __half g_qlin_h[NROW*DD];
__device__ __half g_klin_h[NROW*DD];
__device__ __half g_vlin_h[NROW*DD];
__device__ __half g_qc_h[NROW*DD];
__device__ __half g_kc_h[NROW*DD];
__device__ __half g_vc_h[NROW*DD];
__device__ __half g_hs_h[NROW*DD];
__device__ __half g_wq_h[DD*DD];
__device__ __half g_wk_h[DD*DD];
__device__ __half g_wv_h[DD*DD];
__device__ __half g_wo_h[DD*DD];
__device__ __half g_gw1_h[HID*GINP];
__device__ __half g_gatein_h[NROW*GINP];
__device__ __half g_mix_h[NROW*DD];

// ------------------------- helpers ------------------------------------------
__device__ __forceinline__ unsigned f2tf(float x) {
    unsigned r;
    asm("cvt.rna.tf32.f32 %0, %1;" : "=r"(r) : "f"(x));
    return r;
}

__device__ __forceinline__ void mma_tf32(float* c, const unsigned* a, const unsigned* b) {
    asm volatile(
        "mma.sync.aligned.m16n8k8.row.col.f32.tf32.tf32.f32 "
        "{%0,%1,%2,%3}, {%4,%5,%6,%7}, {%8,%9}, {%0,%1,%2,%3};"
        : "+f"(c[0]), "+f"(c[1]), "+f"(c[2]), "+f"(c[3])
        : "r"(a[0]), "r"(a[1]), "r"(a[2]), "r"(a[3]), "r"(b[0]), "r"(b[1]));
}

__device__ __forceinline__ void mma_f16(float* c, const unsigned* a, const unsigned* b) {
    asm volatile(
        "mma.sync.aligned.m16n8k16.row.col.f32.f16.f16.f32 "
        "{%0,%1,%2,%3}, {%4,%5,%6,%7}, {%8,%9}, {%0,%1,%2,%3};"
        : "+f"(c[0]), "+f"(c[1]), "+f"(c[2]), "+f"(c[3])
        : "r"(a[0]), "r"(a[1]), "r"(a[2]), "r"(a[3]), "r"(b[0]), "r"(b[1]));
}

#define LDSM4(r, addr)                                                        \
    asm volatile("ldmatrix.sync.aligned.m8n8.x4.shared.b16 {%0,%1,%2,%3}, [%4];" \
        : "=r"((r)[0]), "=r"((r)[1]), "=r"((r)[2]), "=r"((r)[3]) : "r"(addr))

// ------------------------- bulk fp32 -> fp16 conversion ---------------------
__global__ __launch_bounds__(256) void cvt_h6(
    const float* __restrict__ s0, __half* __restrict__ d0, int n0,
    const float* __restrict__ s1, __half* __restrict__ d1, int n1,
    const float* __restrict__ s2, __half* __restrict__ d2, int n2,
    const float* __restrict__ s3, __half* __restrict__ d3, int n3,
    const float* __restrict__ s4, __half* __restrict__ d4, int n4,
    const float* __restrict__ s5, __half* __restrict__ d5, int n5)
{
    const float* s; __half* d; int n;
    switch (blockIdx.y) {
        case 0: s=s0; d=d0; n=n0; break;
        case 1: s=s1; d=d1; n=n1; break;
        case 2: s=s2; d=d2; n=n2; break;
        case 3: s=s3; d=d3; n=n3; break;
        case 4: s=s4; d=d4; n=n4; break;
        default: s=s5; d=d5; n=n5; break;
    }
    int i = (blockIdx.x * 256 + threadIdx.x) * 4;
    if (i < n) {
        float4 v = *(const float4*)(s + i);
        __half2 lo = __floats2half2_rn(v.x, v.y);
        __half2 hi = __floats2half2_rn(v.z, v.w);
        uint2 o = {*(unsigned*)&lo, *(unsigned*)&hi};
        *(uint2*)(d + i) = o;
    }
}

// --------- gate_w1 fp32[HID][GIN] -> fp16[HID][GINP] with zero pad ----------
__global__ __launch_bounds__(256) void cvt_gw1pad(const float* __restrict__ src)
{
    int i = (blockIdx.x * 256 + threadIdx.x) * 4;
    if (i >= HID*GINP) return;
    int row = i / GINP, col = i % GINP;
    float4 v;
    if (col < GIN) v = *(const float4*)&src[(size_t)row*GIN + col];
    else v = make_float4(0.f, 0.f, 0.f, 0.f);
    __half2 lo = __floats2half2_rn(v.x, v.y);
    __half2 hi = __floats2half2_rn(v.z, v.w);
    uint2 o = {*(unsigned*)&lo, *(unsigned*)&hi};
    *(uint2*)&g_gw1_h[i] = o;
}

// ---------------- fp16 tensor GEMM: C = A(MxK) @ B(NxK)^T -------------------
// K=64 per stage, 2-stage cp.async pipeline, 128x128 tile, ldmatrix frags.
// mode bit0: +bias, exact GELU.  mode bit1: fp16 out.
#define HSTRB 144
#define HSTAGE_BYTES (128*HSTRB)        // 18432
#define HGEMM_SMEM (4*HSTAGE_BYTES)     // 73728

#define HLOAD64(kt, st) do {                                                   \
    const __half* Ap_ = A + (size_t)bm*K + (kt)*64;                            \
    const __half* Bp_ = B + (size_t)bn*K + (kt)*64;                            \
    _Pragma("unroll")                                                          \
    for (int i_ = 0; i_ < 4; i_++) {                                           \
        int e_ = tid + i_*256;                                                 \
        int row_ = e_ >> 3, seg_ = e_ & 7;                                     \
        unsigned doff_ = (unsigned)row_*HSTRB + (unsigned)seg_*16;             \
        asm volatile("cp.async.cg.shared.global [%0], [%1], 16;"               \
            :: "r"(smb + (unsigned)((st)*HSTAGE_BYTES) + doff_),               \
               "l"(Ap_ + (size_t)row_*K + seg_*8));                            \
        asm volatile("cp.async.cg.shared.global [%0], [%1], 16;"               \
            :: "r"(smb + (unsigned)(2*HSTAGE_BYTES + (st)*HSTAGE_BYTES) + doff_), \
               "l"(Bp_ + (size_t)row_*K + seg_*8));                            \
    }                                                                          \
} while (0)

__global__ __launch_bounds__(256, 2) void hgemm(
    const __half* __restrict__ A,
    const __half* __restrict__ Bm0, const __half* __restrict__ Bm1, const __half* __restrict__ Bm2,
    float* __restrict__ Cm0, float* __restrict__ Cm1, float* __restrict__ Cm2,
    const float* __restrict__ bias, int M, int N, int K, int mode)
{
    extern __shared__ char tsm[];

    const __half* B = (blockIdx.z == 0) ? Bm0 : (blockIdx.z == 1) ? Bm1 : Bm2;
    float*        C = (blockIdx.z == 0) ? Cm0 : (blockIdx.z == 1) ? Cm1 : Cm2;

    int tid = threadIdx.x;
    int bm = blockIdx.y * 128, bn = blockIdx.x * 128;
    unsigned smb;
    asm("{ .reg .u64 t; cvta.to.shared.u64 t, %1; cvt.u32.u64 %0, t; }"
        : "=r"(smb) : "l"(tsm));

    int wid = tid >> 5, lane = tid & 31;
    int wm = (wid >> 2) * 64, wn = (wid & 3) * 32;
    int lr = lane >> 2, lk = lane & 3;

    int a_row = (lane & 7) + ((lane >> 3) & 1) * 8;
    int a_kb  = (lane >> 4) * 16;
    int b_row = (lane & 7) + ((lane >> 4) & 1) * 8;
    int b_kb  = ((lane >> 3) & 1) * 16;

    float acc[4][4][4];
#pragma unroll
    for (int mi = 0; mi < 4; mi++)
#pragma unroll
        for (int ni = 0; ni < 4; ni++)
#pragma unroll
            for (int j = 0; j < 4; j++) acc[mi][ni][j] = 0.f;

    int niter = K >> 6;

    HLOAD64(0, 0);
    asm volatile("cp.async.commit_group;");

    for (int t = 0; t < niter; t++) {
        asm volatile("cp.async.wait_group 0;");
        __syncthreads();
        if (t + 1 < niter) {
            HLOAD64(t + 1, (t + 1) & 1);
            asm volatile("cp.async.commit_group;");
        }
        int cur = t & 1;
        unsigned a_base = smb + (unsigned)(cur*HSTAGE_BYTES);
        unsigned b_base = smb + (unsigned)(2*HSTAGE_BYTES + cur*HSTAGE_BYTES);
#pragma unroll
        for (int ks = 0; ks < 4; ks++) {
            unsigned af[4][4], bq[2][4];
#pragma unroll
            for (int mi = 0; mi < 4; mi++) {
                unsigned addr = a_base + (unsigned)((wm + mi*16 + a_row)*HSTRB + ks*32 + a_kb);
                LDSM4(af[mi], addr);
            }
#pragma unroll
            for (int nq = 0; nq < 2; nq++) {
                unsigned addr = b_base + (unsigned)((wn + nq*16 + b_row)*HSTRB + ks*32 + b_kb);
                LDSM4(bq[nq], addr);
            }
#pragma unroll
            for (int mi = 0; mi < 4; mi++)
#pragma unroll
                for (int ni = 0; ni < 4; ni++)
                    mma_f16(acc[mi][ni], af[mi], &bq[ni >> 1][(ni & 1) * 2]);
        }
        __syncthreads();
    }

#pragma unroll
    for (int mi = 0; mi < 4; mi++) {
        int r0 = bm + wm + mi*16 + lr;
#pragma unroll
        for (int ni = 0; ni < 4; ni++) {
            int c = bn + wn + ni*8 + 2*lk;
            float v[4] = {acc[mi][ni][0], acc[mi][ni][1], acc[mi][ni][2], acc[mi][ni][3]};
            if (mode & 1) {
                float b0 = bias[c], b1 = bias[c+1];
                v[0] += b0; v[1] += b1; v[2] += b0; v[3] += b1;
#pragma unroll
                for (int j = 0; j < 4; j++)
                    v[j] = 0.5f * v[j] * (1.f + erff(v[j] * 0.70710678118654752f));
            }
            if (mode & 2) {
                __half* Ch = (__half*)C;
                *(__half2*)&Ch[(size_t)r0*N + c]     = __floats2half2_rn(v[0], v[1]);
                *(__half2*)&Ch[(size_t)(r0+8)*N + c] = __floats2half2_rn(v[2], v[3]);
            } else {
                float2 lo = {v[0], v[1]};
                float2 hi = {v[2], v[3]};
                *(float2*)&C[(size_t)r0*N + c]       = lo;
                *(float2*)&C[(size_t)(r0+8)*N + c]   = hi;
            }
        }
    }
}

// ------ depthwise causal conv4 + SiLU, smem row-tiled (4 rows/block) --------
__global__ __launch_bounds__(256) void conv4_silu3(
    const __half* __restrict__ x0, const __half* __restrict__ x1, const __half* __restrict__ x2,
    const float* __restrict__ w0, const float* __restrict__ w1, const float* __restrict__ w2,
    __half* __restrict__ y0, __half* __restrict__ y1, __half* __restrict__ y2)
{
    const __half* x; const float* w; __half* y;
    if (blockIdx.y == 0)      { x = x0; w = w0; y = y0; }
    else if (blockIdx.y == 1) { x = x1; w = w1; y = y1; }
    else                      { x = x2; w = w2; y = y2; }
    __shared__ uint2 srow[7][256];

    int rg0 = blockIdx.x * 4;           // first output row (global)
    int l0  = rg0 & (LL - 1);           // position within sequence
    int t = threadIdx.x;                // quad index within row (DD/4 = 256)

#pragma unroll
    for (int j = 0; j < 7; j++) {
        int l = l0 - 3 + j;
        srow[j][t] = (l >= 0)
            ? ((const uint2*)x)[(size_t)(rg0 - 3 + j)*256 + t]
            : make_uint2(0u, 0u);
    }
    __syncthreads();

    int d = t * 4;
    float4 w0v = *(const float4*)(w + d*4);
    float4 w1v = *(const float4*)(w + d*4 + 4);
    float4 w2v = *(const float4*)(w + d*4 + 8);
    float4 w3v = *(const float4*)(w + d*4 + 12);

#pragma unroll
    for (int j = 0; j < 4; j++) {
        float a0 = 0.f, a1 = 0.f, a2 = 0.f, a3 = 0.f;
#pragma unroll
        for (int k = 0; k < 4; k++) {           // tap k: l - 3 + k -> srow[j+k]
            uint2 raw = srow[j + k][t];
            float2 xa = __half22float2(*(__half2*)&raw.x);
            float2 xb = __half22float2(*(__half2*)&raw.y);
            float c0 = (k==0) ? w0v.x : (k==1) ? w0v.y : (k==2) ? w0v.z : w0v.w;
            float c1 = (k==0) ? w1v.x : (k==1) ? w1v.y : (k==2) ? w1v.z : w1v.w;
            float c2 = (k==0) ? w2v.x : (k==1) ? w2v.y : (k==2) ? w2v.z : w2v.w;
            float c3 = (k==0) ? w3v.x : (k==1) ? w3v.y : (k==2) ? w3v.z : w3v.w;
            a0 = fmaf(c0, xa.x, a0);
            a1 = fmaf(c1, xa.y, a1);
            a2 = fmaf(c2, xb.x, a2);
            a3 = fmaf(c3, xb.y, a3);
        }
        a0 = a0 / (1.f + __expf(-a0));
        a1 = a1 / (1.f + __expf(-a1));
        a2 = a2 / (1.f + __expf(-a2));
        a3 = a3 / (1.f + __expf(-a3));
        __half2 o0 = __floats2half2_rn(a0, a1);
        __half2 o1 = __floats2half2_rn(a2, a3);
        uint2 ov = {*(unsigned*)&o0, *(unsigned*)&o1};
        ((uint2*)y)[(size_t)(rg0 + j)*256 + t] = ov;
    }
}

// ------------------- beta = sigmoid(hs_h @ Wb^T) (fp16 hs) ------------------
__global__ __launch_bounds__(128) void beta_kernel(const float* __restrict__ Wb)
{
    __shared__ float red[4][128];
    int n = blockIdx.x, tid = threadIdx.x;
    const __half* hr = g_hs_h + (size_t)n * DD;
    float s0=0,s1=0,s2=0,s3=0;
    for (int i = tid*2; i < DD; i += 256) {
        float2 x = __half22float2(*(const __half2*)&hr[i]);
        s0 += x.x * Wb[i]        + x.y * Wb[i+1];
        s1 += x.x * Wb[DD + i]   + x.y * Wb[DD + i+1];
        s2 += x.x * Wb[2*DD + i] + x.y * Wb[2*DD + i+1];
        s3 += x.x * Wb[3*DD + i] + x.y * Wb[3*DD + i+1];
    }
    red[0][tid]=s0; red[1][tid]=s1; red[2][tid]=s2; red[3][tid]=s3;
    __syncthreads();
    for (int st = 64; st > 0; st >>= 1) {
        if (tid < st)
#pragma unroll
            for (int h = 0; h < 4; h++) red[h][tid] += red[h][tid + st];
        __syncthreads();
    }
    if (tid < 4) g_beta[(size_t)n*HH + tid] = 1.f / (1.f + expf(-red[tid][0]));
}

// ---------------- per-chunk delta-rule precompute (tensor-core mma) ---------
#define PSTR 264
#define PSMEM ((2*32*PSTR + 32*33 + 32*36 + 96) * 4)
__global__ __launch_bounds__(256) void precompute_kernel()
{
    extern __shared__ float psm[];
    float*    Kt  = psm;
    float*    Qt  = Kt + 32*PSTR;
    float*    Am  = Qt + 32*PSTR;
    unsigned* Ttf = (unsigned*)(Am + 32*33);
    float*    bet = (float*)(Ttf + 32*36);
    float*    rnk = bet + 32;
    float*    rnq = rnk + 32;

    int blk = blockIdx.x;
    int c  = blk % NC;
    int bh = blk / NC;
    int h  = bh % HH;
    int b  = bh / HH;
    int tid = threadIdx.x;
    int l0 = c * 32;
    int wid = tid >> 5, lane = tid & 31;
    int lr = lane >> 2, lk = lane & 3;

    for (int e = tid*4; e < 32*256; e += 1024) {
        int r = e >> 8, d = e & 255;
        size_t gb = ((size_t)(b*LL + l0 + r))*DD + h*DV + d;
        uint2 kh = *(const uint2*)&g_kc_h[gb];
        float2 ka = __half22float2(*(__half2*)&kh.x);
        float2 kb2 = __half22float2(*(__half2*)&kh.y);
        *(float4*)&Kt[r*PSTR + d] = make_float4(ka.x, ka.y, kb2.x, kb2.y);
        uint2 qh = *(const uint2*)&g_qc_h[gb];
        float2 qa = __half22float2(*(__half2*)&qh.x);
        float2 qb2 = __half22float2(*(__half2*)&qh.y);
        *(float4*)&Qt[r*PSTR + d] = make_float4(qa.x, qa.y, qb2.x, qb2.y);
    }
    if (tid < 32) bet[tid] = g_beta[((size_t)(b*LL + l0 + tid))*HH + h];
    __syncthreads();

    {
        int r = tid >> 3, part = tid & 7;
        float sk = 0.f, sq = 0.f;
        for (int j = part*32; j < part*32 + 32; j++) {
            float x = Kt[r*PSTR + j]; sk += x*x;
            float y = Qt[r*PSTR + j]; sq += y*y;
        }
        sk += __shfl_down_sync(0xffffffffu, sk, 4, 8);
        sk += __shfl_down_sync(0xffffffffu, sk, 2, 8);
        sk += __shfl_down_sync(0xffffffffu, sk, 1, 8);
        sq += __shfl_down_sync(0xffffffffu, sq, 4, 8);
        sq += __shfl_down_sync(0xffffffffu, sq, 2, 8);
        sq += __shfl_down_sync(0xffffffffu, sq, 1, 8);
        if (part == 0) { rnk[r] = rsqrtf(sk + 1e-6f); rnq[r] = rsqrtf(sq + 1e-6f); }
    }
    __syncthreads();

    size_t obase = (size_t)blk * (32*256);
    for (int e = tid*4; e < 32*256; e += 1024) {
        int r = e >> 8, d = e & 255;
        float rk = rnk[r], rq = rnq[r];
        float4 kv = *(float4*)&Kt[r*PSTR + d];
        kv.x *= rk; kv.y *= rk; kv.z *= rk; kv.w *= rk;
        unsigned* kd = (unsigned*)&Kt[r*PSTR + d];
        kd[0]=f2tf(kv.x); kd[1]=f2tf(kv.y); kd[2]=f2tf(kv.z); kd[3]=f2tf(kv.w);
        float4 qv = *(float4*)&Qt[r*PSTR + d];
        qv.x *= rq; qv.y *= rq; qv.z *= rq; qv.w *= rq;
        __half2 qh0 = __floats2half2_rn(qv.x, qv.y);
        __half2 qh1 = __floats2half2_rn(qv.z, qv.w);
        uint2 qo = {*(unsigned*)&qh0, *(unsigned*)&qh1};
        *(uint2*)&g_qn_h[obase + e] = qo;
        unsigned* qd = (unsigned*)&Qt[r*PSTR + d];
        qd[0]=f2tf(qv.x); qd[1]=f2tf(qv.y); qd[2]=f2tf(qv.z); qd[3]=f2tf(qv.w);
    }
    __syncthreads();

    for (int e = tid*2; e < 32*256; e += 512) {
        int r = e & 31, d = e >> 5;
        float v0 = Kt[r*PSTR + d];
        float v1 = Kt[(r+1)*PSTR + d];
        *(__half2*)&g_knT_h[obase + e] = __floats2half2_rn(v0, v1);
    }

    {
        int m0 = (wid >> 2) * 16, n0 = (wid & 3) * 8;
        const unsigned* Ku = (const unsigned*)Kt;
        const unsigned* Qu = (const unsigned*)Qt;
        float accA[4] = {0,0,0,0}, accQ[4] = {0,0,0,0};
#pragma unroll 4
        for (int kb = 0; kb < 256; kb += 8) {
            unsigned ak[4], aq[4], bf[2];
            ak[0] = Ku[(m0+lr)*PSTR + kb+lk];
            ak[1] = Ku[(m0+lr+8)*PSTR + kb+lk];
            ak[2] = Ku[(m0+lr)*PSTR + kb+lk+4];
            ak[3] = Ku[(m0+lr+8)*PSTR + kb+lk+4];
            aq[0] = Qu[(m0+lr)*PSTR + kb+lk];
            aq[1] = Qu[(m0+lr+8)*PSTR + kb+lk];
            aq[2] = Qu[(m0+lr)*PSTR + kb+lk+4];
            aq[3] = Qu[(m0+lr+8)*PSTR + kb+lk+4];
            bf[0] = Ku[(n0+lr)*PSTR + kb+lk];
            bf[1] = Ku[(n0+lr)*PSTR + kb+lk+4];
            mma_tf32(accA, ak, bf);
            mma_tf32(accQ, aq, bf);
        }
        size_t abase = (size_t)blk * 1024;
        int r0 = m0 + lr, r1 = r0 + 8, c0 = n0 + 2*lk, c1 = c0 + 1;
        float q00 = (c0 <= r0) ? accQ[0] : 0.f;
        float q01 = (c1 <= r0) ? accQ[1] : 0.f;
        float q10 = (c0 <= r1) ? accQ[2] : 0.f;
        float q11 = (c1 <= r1) ? accQ[3] : 0.f;
        *(__half2*)&g_attn_h[abase + r0*32 + c0] = __floats2half2_rn(q00, q01);
        *(__half2*)&g_attn_h[abase + r1*32 + c0] = __floats2half2_rn(q10, q11);
        Am[r0*33 + c0] = (c0 < r0) ? -bet[r0]*accA[0] : 0.f;
        Am[r0*33 + c1] = (c1 < r0) ? -bet[r0]*accA[1] : 0.f;
        Am[r1*33 + c0] = (c0 < r1) ? -bet[r1]*accA[2] : 0.f;
        Am[r1*33 + c1] = (c1 < r1) ? -bet[r1]*accA[3] : 0.f;
    }
    __syncthreads();

    if (tid < 32) {
        int ln = tid;
        for (int i = 1; i < 32; i++) {
            float t = 0.f;
            if (ln < i) for (int p = 0; p < i; p++) t += Am[i*33 + p] * Am[p*33 + ln];
            __syncwarp();
            if (ln < i) Am[i*33 + ln] += t;
            __syncwarp();
        }
    }
    __syncthreads();
    for (int e = tid; e < 1024; e += 256) {
        int i = e >> 5, j = e & 31;
        float t = Am[i*33 + j] + (i == j ? 1.f : 0.f);
        Ttf[i*36 + j] = f2tf(t * bet[j]);
    }
    __syncthreads();
    for (int e = tid*4; e < 32*256; e += 1024) {
        int r = e >> 8, d = e & 255;
        uint2 vh = *(const uint2*)&g_vc_h[((size_t)(b*LL + l0 + r))*DD + h*DV + d];
        float2 va = __half22float2(*(__half2*)&vh.x);
        float2 vb2 = __half22float2(*(__half2*)&vh.y);
        unsigned* qd = (unsigned*)&Qt[r*PSTR + d];
        qd[0]=f2tf(va.x); qd[1]=f2tf(va.y); qd[2]=f2tf(vb2.x); qd[3]=f2tf(vb2.y);
    }
    __syncthreads();

    {
        int m0 = (wid & 1) * 16;
        int nb = (wid >> 1) * 64;
        const unsigned* Ku = (const unsigned*)Kt;
        const unsigned* Vu = (const unsigned*)Qt;
        unsigned a[4][4];
#pragma unroll
        for (int kk = 0; kk < 4; kk++) {
            int kb = kk*8;
            a[kk][0] = Ttf[(m0+lr)*36 + kb+lk];
            a[kk][1] = Ttf[(m0+lr+8)*36 + kb+lk];
            a[kk][2] = Ttf[(m0+lr)*36 + kb+lk+4];
            a[kk][3] = Ttf[(m0+lr+8)*36 + kb+lk+4];
        }
#pragma unroll
        for (int nt = 0; nt < 8; nt++) {
            int n0 = nb + nt*8;
            float au[4] = {0,0,0,0}, aw[4] = {0,0,0,0};
#pragma unroll
            for (int kk = 0; kk < 4; kk++) {
                int kb = kk*8;
                unsigned bu[2], bw[2];
                bu[0] = Vu[(kb+lk)*PSTR + n0+lr];
                bu[1] = Vu[(kb+lk+4)*PSTR + n0+lr];
                bw[0] = Ku[(kb+lk)*PSTR + n0+lr];
                bw[1] = Ku[(kb+lk+4)*PSTR + n0+lr];
                mma_tf32(au, a[kk], bu);
                mma_tf32(aw, a[kk], bw);
            }
            int r0 = m0 + lr, r1 = r0 + 8, cc = n0 + 2*lk;
            *(__half2*)&g_u_h[obase + r0*256 + cc] = __floats2half2_rn(au[0], au[1]);
            *(__half2*)&g_u_h[obase + r1*256 + cc] = __floats2half2_rn(au[2], au[3]);
            *(__half2*)&g_w_h[obase + r0*256 + cc] = __floats2half2_rn(aw[0], aw[1]);
            *(__half2*)&g_w_h[obase + r1*256 + cc] = __floats2half2_rn(aw[2], aw[3]);
        }
    }
}

// --------- sequential inter-chunk scan (fp16 mma, cp.async dbl-buffer) ------
#define BUF_W  0
#define BUF_Q  16896
#define BUF_KT 33792
#define BUF_U  54272        // [32][40] halves (20-word rows)
#define BUF_AT 56832        // [32][40] halves
#define BUF_SIZE 59392
#define SF_OFF 118784       // float [256][40]
#define SH_OFF 159744       // [32][132] words (fp16 S^T shadow)
#define UH_OFF 176640       // [32][20] words (u_i^T fp16)
#define SCAN_SMEM 179200

#define SLOAD(cc, st) do {                                                     \
    size_t base_ = ((size_t)bh*NC + (cc)) * (32*256);                          \
    size_t abase_ = ((size_t)bh*NC + (cc)) * 1024;                             \
    unsigned bb_ = smb + (unsigned)((st)*BUF_SIZE);                            \
    _Pragma("unroll")                                                          \
    for (int i_ = 0; i_ < 4; i_++) {                                           \
        int e_ = (tid + i_*256) * 8;                                           \
        int r_ = e_ >> 8, j_ = e_ & 255;                                       \
        unsigned d_ = (unsigned)(r_*264 + j_) * 2;                             \
        asm volatile("cp.async.cg.shared.global [%0], [%1], 16;"               \
            :: "r"(bb_ + BUF_W + d_), "l"(&g_w_h[base_ + e_]));                \
        asm volatile("cp.async.cg.shared.global [%0], [%1], 16;"               \
            :: "r"(bb_ + BUF_Q + d_), "l"(&g_qn_h[base_ + e_]));               \
        int r2_ = e_ >> 5, j2_ = e_ & 31;                                      \
        asm volatile("cp.async.cg.shared.global [%0], [%1], 16;"               \
            :: "r"(bb_ + BUF_KT + (unsigned)(r2_*40 + j2_)*2),                 \
               "l"(&g_knT_h[base_ + e_]));                                     \
    }                                                                          \
    if (tid < 128) {                                                           \
        int e_ = tid * 8;                                                      \
        int r_ = e_ >> 5, j_ = e_ & 31;                                        \
        asm volatile("cp.async.cg.shared.global [%0], [%1], 16;"               \
            :: "r"(bb_ + BUF_U + (unsigned)(r_*40 + j_)*2),                    \
               "l"(&g_u_h[base_ + r_*256 + g*32 + j_]));                       \
    } else {                                                                   \
        int e_ = (tid - 128) * 8;                                              \
        int r_ = e_ >> 5, j_ = e_ & 31;                                        \
        asm volatile("cp.async.cg.shared.global [%0], [%1], 16;"               \
            :: "r"(bb_ + BUF_AT + (unsigned)(r_*40 + j_)*2),                   \
               "l"(&g_attn_h[abase_ + e_]));                                   \
    }                                                                          \
} while (0)

__global__ __launch_bounds__(256) void scan_kernel()
{
    extern __shared__ char ssm[];
    float*    Sf  = (float*)(ssm + SF_OFF);
    unsigned* Sh  = (unsigned*)(ssm + SH_OFF);
    unsigned* Uh  = (unsigned*)(ssm + UH_OFF);
    __half*   ShH = (__half*)Sh;
    __half*   UhH = (__half*)Uh;
    unsigned smb;
    asm("{ .reg .u64 t; cvta.to.shared.u64 t, %1; cvt.u32.u64 %0, t; }"
        : "=r"(smb) : "l"(ssm));

    int blk = blockIdx.x;
    int g  = blk & (NG-1);
    int bh = blk >> 3;
    int b  = bh >> 2;
    int h  = bh & 3;
    int tid = threadIdx.x;
    int wid = tid >> 5, lane = tid & 31;
    int lr = lane >> 2, lk = lane & 3;
    int m0 = (wid >> 2) * 16;
    int n0 = (wid & 3) * 8;

    for (int e = tid; e < 256*40; e += 256) Sf[e] = 0.f;
    for (int e = tid; e < 32*132; e += 256) Sh[e] = 0u;
    __syncthreads();

    SLOAD(0, 0);
    asm volatile("cp.async.commit_group;");

    for (int c = 0; c < NC; c++) {
        asm volatile("cp.async.wait_group 0;");
        __syncthreads();
        if (c + 1 < NC) SLOAD(c + 1, (c + 1) & 1);
        asm volatile("cp.async.commit_group;");

        int st = c & 1;
        const unsigned* Wt = (const unsigned*)(ssm + st*BUF_SIZE + BUF_W);
        const unsigned* Qt = (const unsigned*)(ssm + st*BUF_SIZE + BUF_Q);
        const unsigned* Kt = (const unsigned*)(ssm + st*BUF_SIZE + BUF_KT);
        const __half*   Ub = (const __half*)(ssm + st*BUF_SIZE + BUF_U);
        const unsigned* Ab = (const unsigned*)(ssm + st*BUF_SIZE + BUF_AT);

        // (1) u_i = u - w@S    (32x32, K=256, fp16)
        {
            float acc[4] = {0.f, 0.f, 0.f, 0.f};
#pragma unroll 4
            for (int kb = 0; kb < 256; kb += 16) {
                int kw = (kb >> 1) + lk;
                unsigned a[4], bf[2];
                a[0] = Wt[(m0+lr)*132 + kw];
                a[1] = Wt[(m0+lr+8)*132 + kw];
                a[2] = Wt[(m0+lr)*132 + kw + 4];
                a[3] = Wt[(m0+lr+8)*132 + kw + 4];
                bf[0] = Sh[(n0+lr)*132 + kw];
                bf[1] = Sh[(n0+lr)*132 + kw + 4];
                mma_f16(acc, a, bf);
            }
            int r0 = m0 + lr, r1 = r0 + 8, cb = n0 + 2*lk;
            float u0 = __half2float(Ub[r0*40 + cb])   - acc[0];
            float u1 = __half2float(Ub[r0*40 + cb+1]) - acc[1];
            float u2 = __half2float(Ub[r1*40 + cb])   - acc[2];
            float u3 = __half2float(Ub[r1*40 + cb+1]) - acc[3];
            UhH[cb*40 + r0]     = __float2half_rn(u0);
            UhH[(cb+1)*40 + r0] = __float2half_rn(u1);
            UhH[cb*40 + r1]     = __float2half_rn(u2);
            UhH[(cb+1)*40 + r1] = __float2half_rn(u3);
        }
        __syncthreads();

        // (2) o = q@S + attn@u_i  -> g_delta (fp16)
        {
            float acc[4] = {0.f, 0.f, 0.f, 0.f};
#pragma unroll 4
            for (int kb = 0; kb < 256; kb += 16) {
                int kw = (kb >> 1) + lk;
                unsigned a[4], bf[2];
                a[0] = Qt[(m0+lr)*132 + kw];
                a[1] = Qt[(m0+lr+8)*132 + kw];
                a[2] = Qt[(m0+lr)*132 + kw + 4];
                a[3] = Qt[(m0+lr+8)*132 + kw + 4];
                bf[0] = Sh[(n0+lr)*132 + kw];
                bf[1] = Sh[(n0+lr)*132 + kw + 4];
                mma_f16(acc, a, bf);
            }
#pragma unroll
            for (int kb = 0; kb < 32; kb += 16) {
                int kw = (kb >> 1) + lk;
                unsigned a[4], bf[2];
                a[0] = Ab[(m0+lr)*20 + kw];
                a[1] = Ab[(m0+lr+8)*20 + kw];
                a[2] = Ab[(m0+lr)*20 + kw + 4];
                a[3] = Ab[(m0+lr+8)*20 + kw + 4];
                bf[0] = Uh[(n0+lr)*20 + kw];
                bf[1] = Uh[(n0+lr)*20 + kw + 4];
                mma_f16(acc, a, bf);
            }
            size_t ob = ((size_t)(b*LL + c*32 + m0 + lr))*DD + h*DV + g*32 + n0 + 2*lk;
            *(__half2*)&g_delta_h[ob]        = __floats2half2_rn(acc[0], acc[1]);
            *(__half2*)&g_delta_h[ob + 8*DD] = __floats2half2_rn(acc[2], acc[3]);
        }
        __syncthreads();

        // (3) S += k^T @ u_i
#pragma unroll
        for (int t = 0; t < 2; t++) {
            int tm = (wid*2 + t) * 16;
#pragma unroll
            for (int tn = 0; tn < 4; tn++) {
                int nn = tn*8;
                int r0 = tm + lr, r1 = r0 + 8, cb = nn + 2*lk;
                float acc[4];
                acc[0] = Sf[r0*40+cb]; acc[1] = Sf[r0*40+cb+1];
                acc[2] = Sf[r1*40+cb]; acc[3] = Sf[r1*40+cb+1];
#pragma unroll
                for (int kb = 0; kb < 32; kb += 16) {
                    int kw = (kb >> 1) + lk;
                    unsigned a[4], bf[2];
                    a[0] = Kt[(tm+lr)*20 + kw];
                    a[1] = Kt[(tm+lr+8)*20 + kw];
                    a[2] = Kt[(tm+lr)*20 + kw + 4];
                    a[3] = Kt[(tm+lr+8)*20 + kw + 4];
                    bf[0] = Uh[(nn+lr)*20 + kw];
                    bf[1] = Uh[(nn+lr)*20 + kw + 4];
                    mma_f16(acc, a, bf);
                }
                Sf[r0*40+cb] = acc[0]; Sf[r0*40+cb+1] = acc[1];
                Sf[r1*40+cb] = acc[2]; Sf[r1*40+cb+1] = acc[3];
                ShH[cb*264 + r0]     = __float2half_rn(acc[0]);
                ShH[(cb+1)*264 + r0] = __float2half_rn(acc[1]);
                ShH[cb*264 + r1]     = __float2half_rn(acc[2]);
                ShH[(cb+1)*264 + r1] = __float2half_rn(acc[3]);
            }
        }
        __syncthreads();
    }
}

// ------ merged FIR conv (K=63 and K=3 from one smem window, fp16 io) --------
__global__ __launch_bounds__(256) void fir_both(
    const float* __restrict__ fw_s, const float* __restrict__ fw_l,
    __half* __restrict__ ys, __half* __restrict__ yl)
{
    __shared__ float2 vbuf[(128 + 62) * 16];
    __shared__ float2 wl[16 * 63];
    __shared__ float2 ws[16 * 3];
    int bh = blockIdx.x;
    int b = bh / HH, h = bh % HH;
    int l0 = blockIdx.y * 128;
    int d0 = blockIdx.z * 32;
    int tid = threadIdx.x;

    for (int idx = tid; idx < 16*63; idx += 256) {
        int dp = idx / 63, t = idx % 63;
        float2 wv;
        wv.x = fw_l[(size_t)(h*DV + d0 + 2*dp)*63 + t];
        wv.y = fw_l[(size_t)(h*DV + d0 + 2*dp + 1)*63 + t];
        wl[dp*63 + t] = wv;
    }
    if (tid < 48) {
        int dp = tid / 3, t = tid % 3;
        float2 wv;
        wv.x = fw_s[(size_t)(h*DV + d0 + 2*dp)*3 + t];
        wv.y = fw_s[(size_t)(h*DV + d0 + 2*dp + 1)*3 + t];
        ws[dp*3 + t] = wv;
    }
    for (int idx = tid; idx < (128 + 62)*16; idx += 256) {
        int lrr = idx >> 4, dp = idx & 15;
        int l = l0 - 62 + lrr;
        vbuf[idx] = (l >= 0)
            ? __half22float2(*(const __half2*)&g_vc_h[((size_t)(b*LL + l))*DD + h*DV + d0 + 2*dp])
            : make_float2(0.f, 0.f);
    }
    __syncthreads();

    int dp = tid & 15;
    int lr0 = (tid >> 4) * 8;
    for (int m = 0; m < 8; m++) {
        int lrr = lr0 + m;
        float2 accL = {0.f, 0.f};
#pragma unroll
        for (int t = 0; t < 63; t++) {
            float2 v = vbuf[(lrr + t)*16 + dp];
            float2 wv = wl[dp*63 + t];
            accL.x = fmaf(v.x, wv.x, accL.x);
            accL.y = fmaf(v.y, wv.y, accL.y);
        }
        float2 accS = {0.f, 0.f};
#pragma unroll
        for (int t = 0; t < 3; t++) {
            float2 v = vbuf[(lrr + 60 + t)*16 + dp];
            float2 wv = ws[dp*3 + t];
            accS.x = fmaf(v.x, wv.x, accS.x);
            accS.y = fmaf(v.y, wv.y, accS.y);
        }
        size_t ob = ((size_t)(b*LL + l0 + lrr))*DD + h*DV + d0 + 2*dp;
        *(__half2*)&yl[ob] = __floats2half2_rn(accL.x, accL.y);
        *(__half2*)&ys[ob] = __floats2half2_rn(accS.x, accS.y);
    }
}

// ------------- gate input assembly (hs + stats), stored as fp16 -------------
__global__ __launch_bounds__(256) void stats_kernel(const float* __restrict__ hs)
{
    int n = blockIdx.x, tid = threadIdx.x;
    {
        int i = tid * 4;
        float4 v = *(const float4*)&hs[(size_t)n*DD + i];
        __half2 lo = __floats2half2_rn(v.x, v.y);
        __half2 hi = __floats2half2_rn(v.z, v.w);
        uint2 o = {*(unsigned*)&lo, *(unsigned*)&hi};
        *(uint2*)&g_gatein_h[(size_t)n*GINP + i] = o;
    }
    if (tid < 32) g_gatein_h[(size_t)n*GINP + GIN + tid] = __float2half_rn(0.f);
    int warp = tid >> 5, lane = tid & 31;
    for (int rep = 0; rep < 2; rep++) {
        int combo = warp*2 + rep;
        int path = combo >> 2, h = combo & 3;
        const __half* p;
        if      (path == 0) p = g_short_h;
        else if (path == 1) p = g_long_h;
        else if (path == 2) p = g_delta_h;
        else                p = g_vc_h;
        p += (size_t)n*DD + h*DV;
        float s1 = 0.f, s2 = 0.f;
        for (int j = lane; j < 256; j += 32) {
            float x = __half2float(p[j]); s1 += x; s2 += x*x;
        }
#pragma unroll
        for (int st = 16; st > 0; st >>= 1) {
            s1 += __shfl_down_sync(0xffffffffu, s1, st);
            s2 += __shfl_down_sync(0xffffffffu, s2, st);
        }
        if (lane == 0) {
            float m  = s1 * (1.f/256.f);
            float va = s2 * (1.f/256.f) - m*m;
            g_gatein_h[(size_t)n*GINP + DD + path*8 + h*2]     = __float2half_rn(m);
            g_gatein_h[(size_t)n*GINP + DD + path*8 + h*2 + 1] = __float2half_rn(va);
        }
    }
}

// ------------------- gate2 + softmax + floor (fp16 hmid) --------------------
__global__ __launch_bounds__(256) void gate2_kernel(
    const float* __restrict__ w2, const float* __restrict__ log_temp,
    const float* __restrict__ base_bias, const float* __restrict__ floor_raw)
{
    __shared__ float hrow[HID];
    __shared__ float lg[16];
    int n = blockIdx.x, tid = threadIdx.x;
    for (int i = tid*2; i < HID; i += 512) {
        float2 v = __half22float2(*(const __half2*)&g_hmid_h[(size_t)n*HID + i]);
        hrow[i] = v.x; hrow[i+1] = v.y;
    }
    __syncthreads();
    int warp = tid >> 5, lane = tid & 31;
    for (int rep = 0; rep < 2; rep++) {
        int o = warp*2 + rep;
        const float* wr = w2 + (size_t)o*HID;
        float s = 0.f;
        for (int i = lane; i < HID; i += 32) s = fmaf(hrow[i], wr[i], s);
#pragma unroll
        for (int st = 16; st > 0; st >>= 1) s += __shfl_down_sync(0xffffffffu, s, st);
        if (lane == 0) lg[o] = s;
    }
    __syncthreads();
    if (tid < 4) {
        int h = tid;
        float temp = log1pf(expf(log_temp[h])) + 1e-4f;
        float z[4], m = -1e30f;
#pragma unroll
        for (int i = 0; i < 4; i++) {
            z[i] = (lg[h*4+i] + base_bias[h*4+i]) / temp;
            m = fmaxf(m, z[i]);
        }
        float e[4], s = 0.f;
#pragma unroll
        for (int i = 0; i < 4; i++) { e[i] = expf(z[i] - m); s += e[i]; }
        float p[4], s2 = 0.f;
#pragma unroll
        for (int i = 0; i < 4; i++) {
            p[i] = e[i] / s;
            float f = 0.05f / (1.f + expf(-floor_raw[h*4+i]));
            p[i] = fmaxf(p[i], f);
            s2 += p[i];
        }
#pragma unroll
        for (int i = 0; i < 4; i++) g_probs[(size_t)n*16 + h*4 + i] = p[i] / s2;
    }
}

// ------------- path mix + RMS norm, output stored as fp16 -------------------
__global__ __launch_bounds__(256) void mix_kernel(const float* __restrict__ onorm)
{
    __shared__ float pr[16];
    __shared__ float wsum[8];
    int n = blockIdx.x, tid = threadIdx.x;
    if (tid < 16) pr[tid] = g_probs[(size_t)n*16 + tid];
    __syncthreads();
    int h = tid >> 6;
    int dd = (tid & 63) * 4;
    size_t pb = (size_t)n*DD + h*DV + dd;
    uint2 sraw = *(const uint2*)&g_short_h[pb];
    uint2 lraw = *(const uint2*)&g_long_h[pb];
    uint2 draw = *(const uint2*)&g_delta_h[pb];
    uint2 vraw = *(const uint2*)&g_vc_h[pb];
    float2 sa = __half22float2(*(__half2*)&sraw.x), sb = __half22float2(*(__half2*)&sraw.y);
    float2 la = __half22float2(*(__half2*)&lraw.x), lb = __half22float2(*(__half2*)&lraw.y);
    float2 da = __half22float2(*(__half2*)&draw.x), db = __half22float2(*(__half2*)&draw.y);
    float2 va = __half22float2(*(__half2*)&vraw.x), vb = __half22float2(*(__half2*)&vraw.y);
    float p0 = pr[h*4+0], p1 = pr[h*4+1], p2 = pr[h*4+2], p3 = pr[h*4+3];
    float o[4];
    o[0] = p0*sa.x + p1*la.x + p2*da.x + p3*va.x;
    o[1] = p0*sa.y + p1*la.y + p2*da.y + p3*va.y;
    o[2] = p0*sb.x + p1*lb.x + p2*db.x + p3*vb.x;
    o[3] = p0*sb.y + p1*lb.y + p2*db.y + p3*vb.y;
    float ss = o[0]*o[0] + o[1]*o[1] + o[2]*o[2] + o[3]*o[3];
#pragma unroll
    for (int st = 16; st > 0; st >>= 1) ss += __shfl_down_sync(0xffffffffu, ss, st);
    int warp = tid >> 5, lane = tid & 31;
    if (lane == 0) wsum[warp] = ss;
    __syncthreads();
    float tot = wsum[h*2] + wsum[h*2+1];
    float scale = rsqrtf(tot * (1.f/256.f) + 1e-5f);
    __half2 h0 = __floats2half2_rn(o[0]*scale*onorm[dd],   o[1]*scale*onorm[dd+1]);
    __half2 h1 = __floats2half2_rn(o[2]*scale*onorm[dd+2], o[3]*scale*onorm[dd+3]);
    uint2 pk = {*(unsigned*)&h0, *(unsigned*)&h1};
    *(uint2*)&g_mix_h[pb] = pk;
}

// ------------------------- launch ------------------------------------------
extern "C" void kernel_launch(void* const* d_in, const int* in_sizes, int n_in,
                              void* d_out, int out_size)
{
    const float* hs        = (const float*)d_in[0];
    const float* Wq        = (const float*)d_in[1];
    const float* Wk        = (const float*)d_in[2];
    const float* Wv        = (const float*)d_in[3];
    const float* Wb        = (const float*)d_in[4];
    const float* qconv_w   = (const float*)d_in[5];
    const float* kconv_w   = (const float*)d_in[6];
    const float* vconv_w   = (const float*)d_in[7];
    const float* fir_s     = (const float*)d_in[8];
    const float* fir_l     = (const float*)d_in[9];
    const float* gate_w1   = (const float*)d_in[10];
    const float* gate_b1   = (const float*)d_in[11];
    const float* gate_w2   = (const float*)d_in[12];
    const float* log_temp  = (const float*)d_in[13];
    const float* base_bias = (const float*)d_in[14];
    const float* floor_raw = (const float*)d_in[15];
    const float* onorm_w   = (const float*)d_in[16];
    const float* Wo        = (const float*)d_in[17];
    float* out = (float*)d_out;

    void *p_qlin, *p_klin, *p_vlin, *p_qc, *p_kc, *p_vc, *p_hmid, *p_short, *p_long;
    void *p_hsh, *p_wqh, *p_wkh, *p_wvh, *p_woh, *p_gw1h, *p_gateinh, *p_mixh;
    cudaGetSymbolAddress(&p_qlin, g_qlin_h);
    cudaGetSymbolAddress(&p_klin, g_klin_h);
    cudaGetSymbolAddress(&p_vlin, g_vlin_h);
    cudaGetSymbolAddress(&p_qc, g_qc_h);
    cudaGetSymbolAddress(&p_kc, g_kc_h);
    cudaGetSymbolAddress(&p_vc, g_vc_h);
    cudaGetSymbolAddress(&p_hmid, g_hmid_h);
    cudaGetSymbolAddress(&p_short, g_short_h);
    cudaGetSymbolAddress(&p_long, g_long_h);
    cudaGetSymbolAddress(&p_hsh, g_hs_h);
    cudaGetSymbolAddress(&p_wqh, g_wq_h);
    cudaGetSymbolAddress(&p_wkh, g_wk_h);
    cudaGetSymbolAddress(&p_wvh, g_wv_h);
    cudaGetSymbolAddress(&p_woh, g_wo_h);
    cudaGetSymbolAddress(&p_gw1h, g_gw1_h);
    cudaGetSymbolAddress(&p_gateinh, g_gatein_h);
    cudaGetSymbolAddress(&p_mixh, g_mix_h);

    cudaFuncSetAttribute(scan_kernel,
        cudaFuncAttributeMaxDynamicSharedMemorySize, SCAN_SMEM);
    cudaFuncSetAttribute(precompute_kernel,
        cudaFuncAttributeMaxDynamicSharedMemorySize, PSMEM);
    cudaFuncSetAttribute(hgemm,
        cudaFuncAttributeMaxDynamicSharedMemorySize, HGEMM_SMEM);

    dim3 blk(256);

    // 0. pre-convert hs + weights to fp16 (gate_w1 padded separately)
    cvt_h6<<<dim3(NROW*DD/1024, 6), blk>>>(
        hs, (__half*)p_hsh, NROW*DD,
        Wq, (__half*)p_wqh, DD*DD,
        Wk, (__half*)p_wkh, DD*DD,
        Wv, (__half*)p_wvh, DD*DD,
        Wo, (__half*)p_woh, DD*DD,
        nullptr, nullptr, 0);
    cvt_gw1pad<<<(HID*GINP/4 + 255)/256, blk>>>(gate_w1);

    // q/k/v projections — fp16 outputs (mode 2)
    hgemm<<<dim3(DD/128, NROW/128, 3), blk, HGEMM_SMEM>>>(
        (const __half*)p_hsh,
        (const __half*)p_wqh, (const __half*)p_wkh, (const __half*)p_wvh,
        (float*)p_qlin, (float*)p_klin, (float*)p_vlin,
        nullptr, NROW, DD, DD, 2);

    // causal conv4 + SiLU (smem row-tiled, 4 rows/block)
    conv4_silu3<<<dim3(NROW/4, 3), blk>>>(
        (const __half*)p_qlin, (const __half*)p_klin, (const __half*)p_vlin,
        qconv_w, kconv_w, vconv_w,
        (__half*)p_qc, (__half*)p_kc, (__half*)p_vc);

    // beta (reads fp16 hs)
    beta_kernel<<<NROW, 128>>>(Wb);

    // delta-rule
    precompute_kernel<<<BB*HH*NC, blk, PSMEM>>>();
    scan_kernel<<<BB*HH*NG, blk, SCAN_SMEM>>>();

    // FIR paths (merged short+long)
    fir_both<<<dim3(BB*HH, LL/128, DV/32), blk>>>(
        fir_s, fir_l, (__half*)p_short, (__half*)p_long);

    // gate (hmid fp16: mode 1|2 = GELU + fp16 out)
    stats_kernel<<<NROW, blk>>>(hs);
    hgemm<<<dim3(HID/128, NROW/128, 1), blk, HGEMM_SMEM>>>(
        (const __half*)p_gateinh,
        (const __half*)p_gw1h, nullptr, nullptr,
        (float*)p_hmid, nullptr, nullptr,
        gate_b1, NROW, HID, GINP, 3);
    gate2_kernel<<<NROW, blk>>>(gate_w2, log_temp, base_bias, floor_raw);

    // mix + RMS norm
    mix_kernel<<<NROW, blk>>>(onorm_w);

    // output projection (fp32 out)
    hgemm<<<dim3(DD/128, NROW/128, 1), blk, HGEMM_SMEM>>>(
        (const __half*)p_mixh,
        (const __half*)p_woh, nullptr, nullptr,
        out, nullptr, nullptr,
        nullptr, NROW, DD, DD, 0);
}